// round 1
// baseline (speedup 1.0000x reference)
#include <cuda_runtime.h>
#include <math.h>

// ---------------- scratch (no allocations allowed) ----------------
__device__ float g_qkv[113246208UL];   // 36864 x 3072
__device__ float g_mid[37748736UL];    // 36864 x 1024

// sigma_act(x) = elu(x)+1 = x>0 ? x+1 : exp(x)
__device__ __forceinline__ float sigma_fn(float x) {
    return x > 0.f ? x + 1.f : expf(x);
}

// ---------------- SGEMM: C[M,N] = A[M,K] @ B[K,N] (+bias) ----------------
#define BM 128
#define BN 128
#define BK 16
#define TM 8
#define TN 8

__global__ __launch_bounds__(256)
void sgemm_kernel(int M, int N, int K,
                  const float* __restrict__ A,
                  const float* __restrict__ B,
                  float* __restrict__ C,
                  const float* __restrict__ bias)
{
    __shared__ float As[BK][BM + 4];   // transposed A tile, padded
    __shared__ float Bs[BK][BN];

    const int tid = threadIdx.x;
    const int tx = tid % 16;
    const int ty = tid / 16;
    const int bx = blockIdx.x;
    const int by = blockIdx.y;

    const float* Ab = A + (size_t)by * BM * K;
    const float* Bb = B + (size_t)bx * BN;

    const int a_row0 = tid >> 2;          // 0..63
    const int a_col  = (tid & 3) * 4;     // 0,4,8,12
    const int b_row0 = tid >> 5;          // 0..7
    const int b_col  = (tid & 31) * 4;

    float acc[TM][TN];
    #pragma unroll
    for (int i = 0; i < TM; i++)
        #pragma unroll
        for (int j = 0; j < TN; j++) acc[i][j] = 0.f;

    for (int k0 = 0; k0 < K; k0 += BK) {
        #pragma unroll
        for (int h = 0; h < 2; h++) {
            int ar = a_row0 + h * 64;
            float4 va = *(const float4*)(Ab + (size_t)ar * K + k0 + a_col);
            As[a_col + 0][ar] = va.x;
            As[a_col + 1][ar] = va.y;
            As[a_col + 2][ar] = va.z;
            As[a_col + 3][ar] = va.w;
        }
        #pragma unroll
        for (int h = 0; h < 2; h++) {
            int br = b_row0 + h * 8;
            float4 vb = *(const float4*)(Bb + (size_t)(k0 + br) * N + b_col);
            *(float4*)(&Bs[br][b_col]) = vb;
        }
        __syncthreads();

        #pragma unroll
        for (int kk = 0; kk < BK; kk++) {
            float a[TM], b[TN];
            #pragma unroll
            for (int i = 0; i < TM; i++) a[i] = As[kk][ty * TM + i];
            #pragma unroll
            for (int j = 0; j < TN; j++) b[j] = Bs[kk][tx * TN + j];
            #pragma unroll
            for (int i = 0; i < TM; i++)
                #pragma unroll
                for (int j = 0; j < TN; j++)
                    acc[i][j] += a[i] * b[j];
        }
        __syncthreads();
    }

    #pragma unroll
    for (int i = 0; i < TM; i++) {
        size_t row = (size_t)by * BM + ty * TM + i;
        int col0 = bx * BN + tx * TN;
        float* Cp = C + row * N + col0;
        #pragma unroll
        for (int j = 0; j < TN; j++) {
            float v = acc[i][j];
            if (bias) v += bias[col0 + j];
            Cp[j] = v;
        }
    }
}

// ---------------- fused attention + memory update per (spatial, head) ----------------
// Shapes: B=2, T=32, Hsp=24, Wsp=24, HEADS=16, DIM_HEAD=64, STRIDE=8
#define TSEQ 32
#define DHD 64

__global__ __launch_bounds__(256)
void attn_kernel(const float* __restrict__ qkv,      // [36864, 3072]
                 const float* __restrict__ mem,      // [18432, 64, 64]
                 const float* __restrict__ zin,      // [18432, 64]
                 const float* __restrict__ mem_beta, // [16]
                 const float* __restrict__ inv_freq, // [32]
                 float* __restrict__ out_mid,        // [36864, 1024]
                 float* __restrict__ new_mem,        // [18432, 64, 64]
                 float* __restrict__ new_z)          // [18432, 64]
{
    __shared__ float qs[TSEQ][DHD + 1];
    __shared__ float ks[TSEQ][DHD + 1];   // raw k -> rotary k -> sigma(q) (reused)
    __shared__ float vs[TSEQ][DHD + 1];
    __shared__ float ms[DHD][DHD + 1];
    __shared__ float sc[TSEQ][TSEQ + 1];
    __shared__ float zs[DHD];
    __shared__ float denom[TSEQ];
    __shared__ float ifr[DHD / 2];

    const int bh   = blockIdx.x;      // s*16 + head
    const int s    = bh >> 4;
    const int head = bh & 15;
    const int b    = s / 576;
    const int rem  = s - b * 576;     // hh*24 + ww
    const int tid  = threadIdx.x;
    // x row index for (b, t, hh, ww) = b*18432 + t*576 + rem
    const int row_base = b * 18432 + rem;

    // ---- load q,k,v (raw), mem, z, inv_freq ----
    for (int e = tid; e < TSEQ * DHD; e += 256) {
        int t = e >> 6, dd = e & 63;
        size_t base = (size_t)(row_base + t * 576) * 3072 + head * 64 + dd;
        qs[t][dd] = qkv[base];
        ks[t][dd] = qkv[base + 1024];
        vs[t][dd] = qkv[base + 2048];
    }
    const size_t mbase = (size_t)bh * (DHD * DHD);
    for (int e = tid; e < DHD * DHD; e += 256)
        ms[e >> 6][e & 63] = mem[mbase + e];
    if (tid < DHD)     zs[tid]  = zin[(size_t)bh * DHD + tid];
    if (tid < DHD / 2) ifr[tid] = inv_freq[tid];
    __syncthreads();

    // ---- new_z = z + sum_t sigma(k_raw[t]) ----
    if (tid < DHD) {
        float acc = zs[tid];
        #pragma unroll
        for (int t = 0; t < TSEQ; t++) acc += sigma_fn(ks[t][tid]);
        new_z[(size_t)bh * DHD + tid] = acc;
    }
    // ---- new_mem = mem + sigma(sigma(k_raw[:8]))^T @ v[:8] ----
    for (int e = tid; e < DHD * DHD; e += 256) {
        int i = e >> 6, j = e & 63;
        float acc = ms[i][j];
        #pragma unroll
        for (int t = 0; t < 8; t++)
            acc += sigma_fn(sigma_fn(ks[t][i])) * vs[t][j];
        new_mem[mbase + e] = acc;
    }
    __syncthreads();

    // ---- rotary on q and k (in place), interleaved pairs ----
    for (int e = tid; e < TSEQ * DHD / 2; e += 256) {
        int t = e >> 5, j = e & 31;
        float sn, cs;
        sincosf((float)t * ifr[j], &sn, &cs);
        float q0 = qs[t][2*j], q1 = qs[t][2*j+1];
        qs[t][2*j]   = q0 * cs - q1 * sn;
        qs[t][2*j+1] = q1 * cs + q0 * sn;
        float k0 = ks[t][2*j], k1 = ks[t][2*j+1];
        ks[t][2*j]   = k0 * cs - k1 * sn;
        ks[t][2*j+1] = k1 * cs + k0 * sn;
    }
    __syncthreads();

    // ---- causal scores = (q @ k^T) * SCALE ----
    for (int e = tid; e < TSEQ * TSEQ; e += 256) {
        int t = e >> 5, tt = e & 31;
        float acc = 0.f;
        if (tt <= t) {
            #pragma unroll
            for (int d = 0; d < DHD; d++) acc += qs[t][d] * ks[tt][d];
            acc *= 0.125f;
        }
        sc[t][tt] = acc;
    }
    __syncthreads();

    // ---- in parallel: sigma(q_rot) -> ks (k no longer needed) ; softmax over rows ----
    for (int e = tid; e < TSEQ * DHD; e += 256) {
        int t = e >> 6, dd = e & 63;
        ks[t][dd] = sigma_fn(qs[t][dd]);
    }
    if (tid < TSEQ) {
        int t = tid;
        float m = -3.4e38f;
        for (int tt = 0; tt <= t; tt++) m = fmaxf(m, sc[t][tt]);
        float ssum = 0.f;
        for (int tt = 0; tt <= t; tt++) {
            float ex = expf(sc[t][tt] - m);
            sc[t][tt] = ex;
            ssum += ex;
        }
        float inv = 1.f / ssum;
        for (int tt = 0; tt <= t; tt++) sc[t][tt] *= inv;
        for (int tt = t + 1; tt < TSEQ; tt++) sc[t][tt] = 0.f;
    }
    __syncthreads();

    // ---- denom[t] = sigma_q[t] . z ----
    if (tid < TSEQ) {
        float acc = 0.f;
        #pragma unroll
        for (int d = 0; d < DHD; d++) acc += ks[tid][d] * zs[d];
        denom[tid] = acc;
    }
    __syncthreads();

    const float g = 1.f / (1.f + expf(-mem_beta[head]));

    // ---- out = g * (sigma_q @ mem)/denom + (1-g) * (attn @ v) ----
    for (int e = tid; e < TSEQ * DHD; e += 256) {
        int t = e >> 6, dd = e & 63;
        float accA = 0.f;
        #pragma unroll
        for (int tt = 0; tt < TSEQ; tt++) accA += sc[t][tt] * vs[tt][dd];
        float accR = 0.f;
        #pragma unroll
        for (int kx = 0; kx < DHD; kx++) accR += ks[t][kx] * ms[kx][dd];
        float val = g * (accR / denom[t]) + (1.f - g) * accA;
        // output layout (B,T,H,W, h*d): row = row_base + t*576, col = head*64+dd
        out_mid[(size_t)(row_base + t * 576) * 1024 + head * 64 + dd] = val;
    }
}

// ---------------- launch ----------------
extern "C" void kernel_launch(void* const* d_in, const int* in_sizes, int n_in,
                              void* d_out, int out_size) {
    const float* x        = (const float*)d_in[0];
    const float* mem      = (const float*)d_in[1];
    const float* z        = (const float*)d_in[2];
    const float* W_qkv    = (const float*)d_in[3];
    const float* W_out    = (const float*)d_in[4];
    const float* b_out    = (const float*)d_in[5];
    const float* mem_beta = (const float*)d_in[6];
    const float* inv_freq = (const float*)d_in[7];

    // outputs concatenated: x_out (37748736), new_mem (75497472), new_z (1179648)
    float* x_out = (float*)d_out;
    float* nmem  = x_out + 37748736UL;
    float* nz    = x_out + 113246208UL;

    float* qkv = nullptr;
    float* mid = nullptr;
    cudaGetSymbolAddress((void**)&qkv, g_qkv);
    cudaGetSymbolAddress((void**)&mid, g_mid);

    const int M = 36864, K = 1024;

    // 1) qkv = x @ W_qkv   [36864 x 3072]
    sgemm_kernel<<<dim3(3072 / BN, M / BM), 256>>>(M, 3072, K, x, W_qkv, qkv, nullptr);

    // 2) fused memory-update + rotary + causal attention + retrieval
    attn_kernel<<<18432, 256>>>(qkv, mem, z, mem_beta, inv_freq, mid, nmem, nz);

    // 3) x_out = mid @ W_out + b_out   [36864 x 1024]
    sgemm_kernel<<<dim3(1024 / BN, M / BM), 256>>>(M, 1024, K, mid, W_out, x_out, b_out);
}

// round 2
// speedup vs baseline: 1.9713x; 1.9713x over previous
#include <cuda_runtime.h>
#include <math.h>

// ---------------- scratch (no allocations allowed) ----------------
__device__ float g_qkv[113246208UL];   // 36864 x 3072
__device__ float g_mid[37748736UL];    // 36864 x 1024

// sigma_act(x) = elu(x)+1 = x>0 ? x+1 : exp(x)
__device__ __forceinline__ float sigma_fn(float x) {
    return x > 0.f ? x + 1.f : expf(x);
}

__device__ __forceinline__ unsigned f2tf32(float x) {
    unsigned r;
    asm("cvt.rna.tf32.f32 %0, %1;\n" : "=r"(r) : "f"(x));
    return r;
}

__device__ __forceinline__ void cp_async16(unsigned smem_addr, const void* gptr) {
    asm volatile("cp.async.cg.shared.global [%0], [%1], 16;\n"
                 :: "r"(smem_addr), "l"(gptr));
}

// ---------------- tf32 tensor-core GEMM: C[M,N] = A[M,K] @ B[K,N] (+bias) ----------
// 128x128x16 block tile, 8 warps of 64x32, mma.m16n8k8.tf32, cp.async double buffer
#define BM 128
#define BN 128
#define BK 16
#define SA 20    // A smem row stride (floats); 20 % 32 == 4 -> conflict-free a-frag LDS
#define SB 136   // B smem row stride (floats); 136 % 32 == 8 -> conflict-free b-frag LDS

__global__ __launch_bounds__(256, 2)
void gemm_tf32(int M, int N, int K,
               const float* __restrict__ A,
               const float* __restrict__ B,
               float* __restrict__ C,
               const float* __restrict__ bias)
{
    __shared__ float As[2][BM * SA];
    __shared__ float Bs[2][BK * SB];

    const int tid   = threadIdx.x;
    const int warp  = tid >> 5;
    const int lane  = tid & 31;
    const int group = lane >> 2;   // 0..7
    const int t4    = lane & 3;    // 0..3
    const int wm0   = (warp & 1) * 64;
    const int wn0   = (warp >> 1) * 32;

    const float* Ab = A + (size_t)blockIdx.y * BM * K;
    const float* Bb = B + (size_t)blockIdx.x * BN;

    // loader indices: each thread copies 2 float4 for A and 2 for B
    const int a_row = tid >> 1;           // 0..127
    const int a_col = (tid & 1) * 8;      // 0 or 8
    const int b_row = tid >> 4;           // 0..15
    const int b_col = (tid & 15) * 8;     // 0..120 step 8

    float acc[4][4][4];
    #pragma unroll
    for (int i = 0; i < 4; i++)
        #pragma unroll
        for (int j = 0; j < 4; j++)
            #pragma unroll
            for (int r = 0; r < 4; r++) acc[i][j][r] = 0.f;

    const int NIT = K / BK;

    // ---- prefetch stage 0 ----
    {
        unsigned sA = (unsigned)__cvta_generic_to_shared(&As[0][a_row * SA + a_col]);
        const float* gA = Ab + (size_t)a_row * K + a_col;
        cp_async16(sA, gA);
        cp_async16(sA + 16, gA + 4);
        unsigned sB = (unsigned)__cvta_generic_to_shared(&Bs[0][b_row * SB + b_col]);
        const float* gB = Bb + (size_t)b_row * N + b_col;
        cp_async16(sB, gB);
        cp_async16(sB + 16, gB + 4);
        asm volatile("cp.async.commit_group;\n");
    }

    for (int it = 0; it < NIT; it++) {
        const int buf = it & 1;
        if (it + 1 < NIT) {
            const int nb = (it + 1) & 1;
            const int k0 = (it + 1) * BK;
            unsigned sA = (unsigned)__cvta_generic_to_shared(&As[nb][a_row * SA + a_col]);
            const float* gA = Ab + (size_t)a_row * K + k0 + a_col;
            cp_async16(sA, gA);
            cp_async16(sA + 16, gA + 4);
            unsigned sB = (unsigned)__cvta_generic_to_shared(&Bs[nb][b_row * SB + b_col]);
            const float* gB = Bb + (size_t)(k0 + b_row) * N + b_col;
            cp_async16(sB, gB);
            cp_async16(sB + 16, gB + 4);
            asm volatile("cp.async.commit_group;\n");
            asm volatile("cp.async.wait_group 1;\n");
        } else {
            asm volatile("cp.async.wait_group 0;\n");
        }
        __syncthreads();

        #pragma unroll
        for (int ks = 0; ks < 2; ks++) {
            const int k0 = ks * 8;
            unsigned a[4][4], b[4][2];
            #pragma unroll
            for (int mt = 0; mt < 4; mt++) {
                const float* p = &As[buf][(wm0 + mt * 16 + group) * SA + k0 + t4];
                a[mt][0] = f2tf32(p[0]);
                a[mt][1] = f2tf32(p[8 * SA]);
                a[mt][2] = f2tf32(p[4]);
                a[mt][3] = f2tf32(p[8 * SA + 4]);
            }
            #pragma unroll
            for (int nt = 0; nt < 4; nt++) {
                const float* p = &Bs[buf][(k0 + t4) * SB + wn0 + nt * 8 + group];
                b[nt][0] = f2tf32(p[0]);
                b[nt][1] = f2tf32(p[4 * SB]);
            }
            #pragma unroll
            for (int mt = 0; mt < 4; mt++)
                #pragma unroll
                for (int nt = 0; nt < 4; nt++) {
                    asm volatile(
                        "mma.sync.aligned.m16n8k8.row.col.f32.tf32.tf32.f32 "
                        "{%0,%1,%2,%3}, {%4,%5,%6,%7}, {%8,%9}, {%0,%1,%2,%3};\n"
                        : "+f"(acc[mt][nt][0]), "+f"(acc[mt][nt][1]),
                          "+f"(acc[mt][nt][2]), "+f"(acc[mt][nt][3])
                        : "r"(a[mt][0]), "r"(a[mt][1]), "r"(a[mt][2]), "r"(a[mt][3]),
                          "r"(b[nt][0]), "r"(b[nt][1]));
                }
        }
        __syncthreads();
    }

    // ---- epilogue ----
    #pragma unroll
    for (int mt = 0; mt < 4; mt++) {
        const size_t row0 = (size_t)blockIdx.y * BM + wm0 + mt * 16 + group;
        const size_t row1 = row0 + 8;
        #pragma unroll
        for (int nt = 0; nt < 4; nt++) {
            const int col = blockIdx.x * BN + wn0 + nt * 8 + t4 * 2;
            float b0 = 0.f, b1 = 0.f;
            if (bias) { b0 = bias[col]; b1 = bias[col + 1]; }
            float2 v0 = make_float2(acc[mt][nt][0] + b0, acc[mt][nt][1] + b1);
            float2 v1 = make_float2(acc[mt][nt][2] + b0, acc[mt][nt][3] + b1);
            *(float2*)(C + row0 * N + col) = v0;
            *(float2*)(C + row1 * N + col) = v1;
        }
    }
}

// ---------------- fused attention + memory update per (spatial, head) ----------------
// Shapes: B=2, T=32, Hsp=24, Wsp=24, HEADS=16, DIM_HEAD=64, STRIDE=8
#define TSEQ 32
#define DHD 64

__global__ __launch_bounds__(256)
void attn_kernel(const float* __restrict__ qkv,      // [36864, 3072]
                 const float* __restrict__ mem,      // [18432, 64, 64]
                 const float* __restrict__ zin,      // [18432, 64]
                 const float* __restrict__ mem_beta, // [16]
                 const float* __restrict__ inv_freq, // [32]
                 float* __restrict__ out_mid,        // [36864, 1024]
                 float* __restrict__ new_mem,        // [18432, 64, 64]
                 float* __restrict__ new_z)          // [18432, 64]
{
    __shared__ float qs[TSEQ][DHD + 1];
    __shared__ float ks[TSEQ][DHD + 1];   // raw k -> rotary k -> sigma(q) (reused)
    __shared__ float vs[TSEQ][DHD + 1];
    __shared__ float ms[DHD][DHD + 1];
    __shared__ float sc[TSEQ][TSEQ + 1];
    __shared__ float zs[DHD];
    __shared__ float denom[TSEQ];
    __shared__ float ifr[DHD / 2];

    const int bh   = blockIdx.x;      // s*16 + head
    const int s    = bh >> 4;
    const int head = bh & 15;
    const int b    = s / 576;
    const int rem  = s - b * 576;     // hh*24 + ww
    const int tid  = threadIdx.x;
    const int row_base = b * 18432 + rem;

    // ---- load q,k,v (raw), mem, z, inv_freq ----
    for (int e = tid; e < TSEQ * DHD; e += 256) {
        int t = e >> 6, dd = e & 63;
        size_t base = (size_t)(row_base + t * 576) * 3072 + head * 64 + dd;
        qs[t][dd] = qkv[base];
        ks[t][dd] = qkv[base + 1024];
        vs[t][dd] = qkv[base + 2048];
    }
    const size_t mbase = (size_t)bh * (DHD * DHD);
    for (int e = tid; e < DHD * DHD; e += 256)
        ms[e >> 6][e & 63] = mem[mbase + e];
    if (tid < DHD)     zs[tid]  = zin[(size_t)bh * DHD + tid];
    if (tid < DHD / 2) ifr[tid] = inv_freq[tid];
    __syncthreads();

    // ---- new_z = z + sum_t sigma(k_raw[t]) ----
    if (tid < DHD) {
        float acc = zs[tid];
        #pragma unroll
        for (int t = 0; t < TSEQ; t++) acc += sigma_fn(ks[t][tid]);
        new_z[(size_t)bh * DHD + tid] = acc;
    }
    // ---- new_mem = mem + sigma(sigma(k_raw[:8]))^T @ v[:8] ----
    for (int e = tid; e < DHD * DHD; e += 256) {
        int i = e >> 6, j = e & 63;
        float acc = ms[i][j];
        #pragma unroll
        for (int t = 0; t < 8; t++)
            acc += sigma_fn(sigma_fn(ks[t][i])) * vs[t][j];
        new_mem[mbase + e] = acc;
    }
    __syncthreads();

    // ---- rotary on q and k (in place), interleaved pairs ----
    for (int e = tid; e < TSEQ * DHD / 2; e += 256) {
        int t = e >> 5, j = e & 31;
        float sn, cs;
        sincosf((float)t * ifr[j], &sn, &cs);
        float q0 = qs[t][2*j], q1 = qs[t][2*j+1];
        qs[t][2*j]   = q0 * cs - q1 * sn;
        qs[t][2*j+1] = q1 * cs + q0 * sn;
        float k0 = ks[t][2*j], k1 = ks[t][2*j+1];
        ks[t][2*j]   = k0 * cs - k1 * sn;
        ks[t][2*j+1] = k1 * cs + k0 * sn;
    }
    __syncthreads();

    // ---- causal scores = (q @ k^T) * SCALE ----
    for (int e = tid; e < TSEQ * TSEQ; e += 256) {
        int t = e >> 5, tt = e & 31;
        float acc = 0.f;
        if (tt <= t) {
            #pragma unroll
            for (int d = 0; d < DHD; d++) acc += qs[t][d] * ks[tt][d];
            acc *= 0.125f;
        }
        sc[t][tt] = acc;
    }
    __syncthreads();

    // ---- sigma(q_rot) -> ks ; softmax over rows ----
    for (int e = tid; e < TSEQ * DHD; e += 256) {
        int t = e >> 6, dd = e & 63;
        ks[t][dd] = sigma_fn(qs[t][dd]);
    }
    if (tid < TSEQ) {
        int t = tid;
        float m = -3.4e38f;
        for (int tt = 0; tt <= t; tt++) m = fmaxf(m, sc[t][tt]);
        float ssum = 0.f;
        for (int tt = 0; tt <= t; tt++) {
            float ex = expf(sc[t][tt] - m);
            sc[t][tt] = ex;
            ssum += ex;
        }
        float inv = 1.f / ssum;
        for (int tt = 0; tt <= t; tt++) sc[t][tt] *= inv;
        for (int tt = t + 1; tt < TSEQ; tt++) sc[t][tt] = 0.f;
    }
    __syncthreads();

    // ---- denom[t] = sigma_q[t] . z ----
    if (tid < TSEQ) {
        float acc = 0.f;
        #pragma unroll
        for (int d = 0; d < DHD; d++) acc += ks[tid][d] * zs[d];
        denom[tid] = acc;
    }
    __syncthreads();

    const float g = 1.f / (1.f + expf(-mem_beta[head]));

    // ---- out = g * (sigma_q @ mem)/denom + (1-g) * (attn @ v) ----
    for (int e = tid; e < TSEQ * DHD; e += 256) {
        int t = e >> 6, dd = e & 63;
        float accA = 0.f;
        #pragma unroll
        for (int tt = 0; tt < TSEQ; tt++) accA += sc[t][tt] * vs[tt][dd];
        float accR = 0.f;
        #pragma unroll
        for (int kx = 0; kx < DHD; kx++) accR += ks[t][kx] * ms[kx][dd];
        float val = g * (accR / denom[t]) + (1.f - g) * accA;
        out_mid[(size_t)(row_base + t * 576) * 1024 + head * 64 + dd] = val;
    }
}

// ---------------- launch ----------------
extern "C" void kernel_launch(void* const* d_in, const int* in_sizes, int n_in,
                              void* d_out, int out_size) {
    const float* x        = (const float*)d_in[0];
    const float* mem      = (const float*)d_in[1];
    const float* z        = (const float*)d_in[2];
    const float* W_qkv    = (const float*)d_in[3];
    const float* W_out    = (const float*)d_in[4];
    const float* b_out    = (const float*)d_in[5];
    const float* mem_beta = (const float*)d_in[6];
    const float* inv_freq = (const float*)d_in[7];

    // outputs concatenated: x_out (37748736), new_mem (75497472), new_z (1179648)
    float* x_out = (float*)d_out;
    float* nmem  = x_out + 37748736UL;
    float* nz    = x_out + 113246208UL;

    float* qkv = nullptr;
    float* mid = nullptr;
    cudaGetSymbolAddress((void**)&qkv, g_qkv);
    cudaGetSymbolAddress((void**)&mid, g_mid);

    const int M = 36864, K = 1024;

    // 1) qkv = x @ W_qkv   [36864 x 3072]
    gemm_tf32<<<dim3(3072 / BN, M / BM), 256>>>(M, 3072, K, x, W_qkv, qkv, nullptr);

    // 2) fused memory-update + rotary + causal attention + retrieval
    attn_kernel<<<18432, 256>>>(qkv, mem, z, mem_beta, inv_freq, mid, nmem, nz);

    // 3) x_out = mid @ W_out + b_out   [36864 x 1024]
    gemm_tf32<<<dim3(1024 / BN, M / BM), 256>>>(M, 1024, K, mid, W_out, x_out, b_out);
}

// round 5
// speedup vs baseline: 2.5920x; 1.3149x over previous
#include <cuda_runtime.h>
#include <cuda_fp16.h>
#include <math.h>
#include <stdint.h>

// ---------------- scratch (no allocations allowed) ----------------
__device__ __half g_qkv_h[113246208UL];  // 36864 x 3072 (GEMM1 out, fp16)
__device__ __half g_mid_h[37748736UL];   // 36864 x 1024 (attn out, fp16, K-permuted)
__device__ __half g_x_h[37748736UL];     // x converted to fp16, K-permuted
__device__ __half g_wt_h[4194304UL];     // Wt_qkv [3072,1024] + Wt_out [1024,1024], K-permuted

__device__ __forceinline__ float sigma_fn(float x) {
    return x > 0.f ? x + 1.f : expf(x);
}
__device__ __forceinline__ void cp_async16(uint32_t saddr, const void* gptr) {
    asm volatile("cp.async.cg.shared.global [%0], [%1], 16;\n" :: "r"(saddr), "l"(gptr));
}
__device__ __forceinline__ uint32_t smem_u32(const void* p) {
    uint32_t a;
    asm("{ .reg .u64 t; cvta.to.shared.u64 t, %1; cvt.u32.u64 %0, t; }" : "=r"(a) : "l"(p));
    return a;
}

// K-interleave permutation within each 16-element group.
// Source j lands at dest perm16(j) = [0,1,4,5,8,9,12,13,2,3,6,7,10,11,14,15][j]
// so that contiguous halves 4*t4..4*t4+3 hold original k {2t4,2t4+1,2t4+8,2t4+9}.
__host__ __device__ __forceinline__ int perm16(int j) {
    return ((j >> 1) & 3) * 4 + ((j >> 3) & 1) * 2 + (j & 1);
}
// inverse: source index for dest position o
__host__ __device__ __forceinline__ int iperm16(int o) {
    return ((o >> 2) & 3) * 2 + ((o >> 1) & 1) * 8 + (o & 1);
}

// ================= fp16 mma.sync GEMM =================
// C[M,N] = A[M,K] @ Bt[N,K]^T (+bias). A, Bt fp16 with K-permuted columns.
// 128x128 CTA tile, BK=32 halves/stage, 4-stage cp.async, 8 warps of 64x32,
// mma.sync.m16n8k16.f32.f16.f16.f32
#define GSTAGES 4
#define ROWB 96                 // padded row bytes in smem (64B data + 32B pad)
#define STAGE_BYTES (128 * ROWB)                // 12288
#define BOFF (GSTAGES * STAGE_BYTES)            // B tiles after A tiles
#define GEMM_SMEM (2 * GSTAGES * STAGE_BYTES)   // 98304

template<bool HALF_OUT>
__global__ __launch_bounds__(256, 2)
void gemm_h(int N, int K,
            const __half* __restrict__ A,
            const __half* __restrict__ Bt,
            void* __restrict__ Cout,
            const float* __restrict__ bias)
{
    extern __shared__ char smem[];
    const uint32_t sbase = smem_u32(smem);
    const int tid  = threadIdx.x;
    const int warp = tid >> 5;
    const int lane = tid & 31;
    const int g    = lane >> 2;   // 0..7
    const int t4   = lane & 3;    // 0..3
    const int wm0  = (warp & 1) * 64;
    const int wn0  = (warp >> 1) * 32;

    const size_t m0 = (size_t)blockIdx.y * 128;
    const size_t n0 = (size_t)blockIdx.x * 128;

    // loader: each thread copies 2x16B of A and 2x16B of B per stage
    const int lrow = tid >> 1;       // 0..127
    const int lhalf = tid & 1;       // 0 or 1 (which 32B half of the 64B row chunk)
    const __half* gA = A + (m0 + lrow) * K + lhalf * 16;
    const __half* gB = Bt + (n0 + lrow) * K + lhalf * 16;
    const uint32_t sArow = sbase + lrow * ROWB + lhalf * 32;
    const uint32_t sBrow = sbase + BOFF + lrow * ROWB + lhalf * 32;

    const int nchunks = K >> 5;   // K / 32

    float acc[4][4][4];
    #pragma unroll
    for (int i = 0; i < 4; i++)
        #pragma unroll
        for (int j = 0; j < 4; j++) {
            acc[i][j][0] = 0.f; acc[i][j][1] = 0.f;
            acc[i][j][2] = 0.f; acc[i][j][3] = 0.f;
        }

    // prologue: stages 0..2
    #pragma unroll
    for (int s = 0; s < 3; s++) {
        const __half* pa = gA + s * 32;
        const __half* pb = gB + s * 32;
        uint32_t sa = sArow + s * STAGE_BYTES;
        uint32_t sb = sBrow + s * STAGE_BYTES;
        cp_async16(sa, pa);       cp_async16(sa + 16, pa + 8);
        cp_async16(sb, pb);       cp_async16(sb + 16, pb + 8);
        asm volatile("cp.async.commit_group;\n");
    }

    for (int c = 0; c < nchunks; c++) {
        asm volatile("cp.async.wait_group 2;\n");
        __syncthreads();

        const int nc = c + 3;
        if (nc < nchunks) {
            const int ns = nc & 3;
            const __half* pa = gA + nc * 32;
            const __half* pb = gB + nc * 32;
            uint32_t sa = sArow + ns * STAGE_BYTES;
            uint32_t sb = sBrow + ns * STAGE_BYTES;
            cp_async16(sa, pa);   cp_async16(sa + 16, pa + 8);
            cp_async16(sb, pb);   cp_async16(sb + 16, pb + 8);
        }
        asm volatile("cp.async.commit_group;\n");

        const int s = c & 3;
        const char* aS = smem + s * STAGE_BYTES;
        const char* bS = smem + BOFF + s * STAGE_BYTES;

        #pragma unroll
        for (int ks = 0; ks < 2; ks++) {
            uint32_t a[4][4], b[4][2];
            #pragma unroll
            for (int mt = 0; mt < 4; mt++) {
                const char* p = aS + (wm0 + mt * 16 + g) * ROWB + ks * 32 + t4 * 8;
                uint2 lo = *(const uint2*)p;              // row g
                uint2 hi = *(const uint2*)(p + 8 * ROWB); // row g+8
                a[mt][0] = lo.x; a[mt][1] = hi.x; a[mt][2] = lo.y; a[mt][3] = hi.y;
            }
            #pragma unroll
            for (int nt = 0; nt < 4; nt++) {
                const char* p = bS + (wn0 + nt * 8 + g) * ROWB + ks * 32 + t4 * 8;
                uint2 bb = *(const uint2*)p;
                b[nt][0] = bb.x; b[nt][1] = bb.y;
            }
            #pragma unroll
            for (int mt = 0; mt < 4; mt++)
                #pragma unroll
                for (int nt = 0; nt < 4; nt++) {
                    asm volatile(
                        "mma.sync.aligned.m16n8k16.row.col.f32.f16.f16.f32 "
                        "{%0,%1,%2,%3}, {%4,%5,%6,%7}, {%8,%9}, {%0,%1,%2,%3};\n"
                        : "+f"(acc[mt][nt][0]), "+f"(acc[mt][nt][1]),
                          "+f"(acc[mt][nt][2]), "+f"(acc[mt][nt][3])
                        : "r"(a[mt][0]), "r"(a[mt][1]), "r"(a[mt][2]), "r"(a[mt][3]),
                          "r"(b[nt][0]), "r"(b[nt][1]));
                }
        }
    }

    // ---- epilogue ----
    #pragma unroll
    for (int mt = 0; mt < 4; mt++) {
        const size_t r0 = m0 + wm0 + mt * 16 + g;
        const size_t r1 = r0 + 8;
        #pragma unroll
        for (int nt = 0; nt < 4; nt++) {
            const int col = (int)n0 + wn0 + nt * 8 + t4 * 2;
            if (HALF_OUT) {
                __half* C = (__half*)Cout;
                *(__half2*)(C + r0 * N + col) = __floats2half2_rn(acc[mt][nt][0], acc[mt][nt][1]);
                *(__half2*)(C + r1 * N + col) = __floats2half2_rn(acc[mt][nt][2], acc[mt][nt][3]);
            } else {
                float* C = (float*)Cout;
                float b0 = bias ? bias[col] : 0.f;
                float b1 = bias ? bias[col + 1] : 0.f;
                *(float2*)(C + r0 * N + col) = make_float2(acc[mt][nt][0] + b0, acc[mt][nt][1] + b1);
                *(float2*)(C + r1 * N + col) = make_float2(acc[mt][nt][2] + b0, acc[mt][nt][3] + b1);
            }
        }
    }
}

// ---------------- preprocessing ----------------
// x [rows, K] f32 -> half with per-16 K-permutation (FIXED: full 32B store)
__global__ __launch_bounds__(256)
void convert_x_kernel(const float* __restrict__ in, __half* __restrict__ out, int ngroups) {
    int idx = blockIdx.x * 256 + threadIdx.x;
    if (idx >= ngroups) return;
    const float* p = in + (size_t)idx * 16;
    __half h[16];
    #pragma unroll
    for (int o = 0; o < 16; o++)
        h[o] = __float2half_rn(p[iperm16(o)]);
    uint4* o4 = (uint4*)(out + (size_t)idx * 16);
    o4[0] = ((const uint4*)h)[0];   // halves 0..7
    o4[1] = ((const uint4*)h)[1];   // halves 8..15
}

// W [Kk, Nn] f32 -> Wt [Nn, Kk] half with per-16 K-permutation (FIXED: full 32B store)
__global__ __launch_bounds__(256)
void transpose_half_kernel(const float* __restrict__ in, __half* __restrict__ out,
                           int Kk, int Nn) {
    __shared__ float t[32][33];
    const int n0 = blockIdx.x * 32;
    const int k0 = blockIdx.y * 32;
    const int tx = threadIdx.x & 31;
    const int ty = threadIdx.x >> 5;  // 0..7
    #pragma unroll
    for (int r = 0; r < 4; r++) {
        int kr = ty + r * 8;
        t[kr][tx] = in[(size_t)(k0 + kr) * Nn + n0 + tx];
    }
    __syncthreads();
    if (threadIdx.x < 64) {
        const int nl = threadIdx.x >> 1;
        const int kg = threadIdx.x & 1;
        __half h[16];
        #pragma unroll
        for (int o = 0; o < 16; o++)
            h[o] = __float2half_rn(t[kg * 16 + iperm16(o)][nl]);
        uint4* o4 = (uint4*)(out + (size_t)(n0 + nl) * Kk + k0 + kg * 16);
        o4[0] = ((const uint4*)h)[0];
        o4[1] = ((const uint4*)h)[1];
    }
}

// ---------------- fused attention + memory update per (spatial, head) ----------------
#define TSEQ 32
#define DHD 64

__global__ __launch_bounds__(256)
void attn_kernel(const __half* __restrict__ qkv,     // [36864, 3072] fp16
                 const float* __restrict__ mem,
                 const float* __restrict__ zin,
                 const float* __restrict__ mem_beta,
                 const float* __restrict__ inv_freq,
                 __half* __restrict__ out_mid,       // [36864, 1024] fp16, K-permuted
                 float* __restrict__ new_mem,
                 float* __restrict__ new_z)
{
    __shared__ float qs[TSEQ][DHD + 1];
    __shared__ float ks[TSEQ][DHD + 1];
    __shared__ float vs[TSEQ][DHD + 1];
    __shared__ float ms[DHD][DHD + 1];
    __shared__ float sc[TSEQ][TSEQ + 1];
    __shared__ float zs[DHD];
    __shared__ float denom[TSEQ];
    __shared__ float ifr[DHD / 2];

    const int bh   = blockIdx.x;
    const int s    = bh >> 4;
    const int head = bh & 15;
    const int b    = s / 576;
    const int rem  = s - b * 576;
    const int tid  = threadIdx.x;
    const int row_base = b * 18432 + rem;

    for (int e = tid; e < TSEQ * DHD; e += 256) {
        int t = e >> 6, dd = e & 63;
        size_t base = (size_t)(row_base + t * 576) * 3072 + head * 64 + dd;
        qs[t][dd] = __half2float(qkv[base]);
        ks[t][dd] = __half2float(qkv[base + 1024]);
        vs[t][dd] = __half2float(qkv[base + 2048]);
    }
    const size_t mbase = (size_t)bh * (DHD * DHD);
    for (int e = tid; e < DHD * DHD; e += 256)
        ms[e >> 6][e & 63] = mem[mbase + e];
    if (tid < DHD)     zs[tid]  = zin[(size_t)bh * DHD + tid];
    if (tid < DHD / 2) ifr[tid] = inv_freq[tid];
    __syncthreads();

    if (tid < DHD) {
        float acc = zs[tid];
        #pragma unroll
        for (int t = 0; t < TSEQ; t++) acc += sigma_fn(ks[t][tid]);
        new_z[(size_t)bh * DHD + tid] = acc;
    }
    for (int e = tid; e < DHD * DHD; e += 256) {
        int i = e >> 6, j = e & 63;
        float acc = ms[i][j];
        #pragma unroll
        for (int t = 0; t < 8; t++)
            acc += sigma_fn(sigma_fn(ks[t][i])) * vs[t][j];
        new_mem[mbase + e] = acc;
    }
    __syncthreads();

    for (int e = tid; e < TSEQ * DHD / 2; e += 256) {
        int t = e >> 5, j = e & 31;
        float sn, cs;
        sincosf((float)t * ifr[j], &sn, &cs);
        float q0 = qs[t][2*j], q1 = qs[t][2*j+1];
        qs[t][2*j]   = q0 * cs - q1 * sn;
        qs[t][2*j+1] = q1 * cs + q0 * sn;
        float k0 = ks[t][2*j], k1 = ks[t][2*j+1];
        ks[t][2*j]   = k0 * cs - k1 * sn;
        ks[t][2*j+1] = k1 * cs + k0 * sn;
    }
    __syncthreads();

    for (int e = tid; e < TSEQ * TSEQ; e += 256) {
        int t = e >> 5, tt = e & 31;
        float acc = 0.f;
        if (tt <= t) {
            #pragma unroll
            for (int d = 0; d < DHD; d++) acc += qs[t][d] * ks[tt][d];
            acc *= 0.125f;
        }
        sc[t][tt] = acc;
    }
    __syncthreads();

    for (int e = tid; e < TSEQ * DHD; e += 256) {
        int t = e >> 6, dd = e & 63;
        ks[t][dd] = sigma_fn(qs[t][dd]);
    }
    if (tid < TSEQ) {
        int t = tid;
        float m = -3.4e38f;
        for (int tt = 0; tt <= t; tt++) m = fmaxf(m, sc[t][tt]);
        float ssum = 0.f;
        for (int tt = 0; tt <= t; tt++) {
            float ex = expf(sc[t][tt] - m);
            sc[t][tt] = ex;
            ssum += ex;
        }
        float inv = 1.f / ssum;
        for (int tt = 0; tt <= t; tt++) sc[t][tt] *= inv;
        for (int tt = t + 1; tt < TSEQ; tt++) sc[t][tt] = 0.f;
    }
    __syncthreads();

    if (tid < TSEQ) {
        float acc = 0.f;
        #pragma unroll
        for (int d = 0; d < DHD; d++) acc += ks[tid][d] * zs[d];
        denom[tid] = acc;
    }
    __syncthreads();

    const float g = 1.f / (1.f + expf(-mem_beta[head]));

    for (int e = tid; e < TSEQ * DHD; e += 256) {
        int t = e >> 6, dd = e & 63;
        float accA = 0.f;
        #pragma unroll
        for (int tt = 0; tt < TSEQ; tt++) accA += sc[t][tt] * vs[tt][dd];
        float accR = 0.f;
        #pragma unroll
        for (int kx = 0; kx < DHD; kx++) accR += ks[t][kx] * ms[kx][dd];
        float val = g * (accR / denom[t]) + (1.f - g) * accA;
        // store fp16 with K-permutation (mid is GEMM2's A operand)
        int pdd = (dd & ~15) | perm16(dd & 15);
        out_mid[(size_t)(row_base + t * 576) * 1024 + head * 64 + pdd] = __float2half_rn(val);
    }
}

// ---------------- launch ----------------
extern "C" void kernel_launch(void* const* d_in, const int* in_sizes, int n_in,
                              void* d_out, int out_size) {
    const float* x        = (const float*)d_in[0];
    const float* mem      = (const float*)d_in[1];
    const float* z        = (const float*)d_in[2];
    const float* W_qkv    = (const float*)d_in[3];
    const float* W_out    = (const float*)d_in[4];
    const float* b_out    = (const float*)d_in[5];
    const float* mem_beta = (const float*)d_in[6];
    const float* inv_freq = (const float*)d_in[7];

    float* x_out = (float*)d_out;
    float* nmem  = x_out + 37748736UL;
    float* nz    = x_out + 113246208UL;

    __half *qkv = nullptr, *mid = nullptr, *xh = nullptr, *wt = nullptr;
    cudaGetSymbolAddress((void**)&qkv, g_qkv_h);
    cudaGetSymbolAddress((void**)&mid, g_mid_h);
    cudaGetSymbolAddress((void**)&xh, g_x_h);
    cudaGetSymbolAddress((void**)&wt, g_wt_h);
    __half* wt_qkv = wt;                 // [3072,1024]
    __half* wt_out = wt + 3145728UL;     // [1024,1024]

    cudaFuncSetAttribute(gemm_h<true>, cudaFuncAttributeMaxDynamicSharedMemorySize, GEMM_SMEM);
    cudaFuncSetAttribute(gemm_h<false>, cudaFuncAttributeMaxDynamicSharedMemorySize, GEMM_SMEM);

    const int M = 36864, K = 1024;

    // 0) preprocessing: x -> fp16 (permuted); weights -> transposed fp16 (permuted)
    convert_x_kernel<<<(M * K / 16 + 255) / 256, 256>>>(x, xh, M * K / 16);
    transpose_half_kernel<<<dim3(3072 / 32, 1024 / 32), 256>>>(W_qkv, wt_qkv, 1024, 3072);
    transpose_half_kernel<<<dim3(1024 / 32, 1024 / 32), 256>>>(W_out, wt_out, 1024, 1024);

    // 1) qkv = x @ W_qkv  (fp16 mma, fp16 out)
    gemm_h<true><<<dim3(3072 / 128, M / 128), 256, GEMM_SMEM>>>(
        3072, K, xh, wt_qkv, qkv, nullptr);

    // 2) fused memory-update + rotary + causal attention + retrieval
    attn_kernel<<<18432, 256>>>(qkv, mem, z, mem_beta, inv_freq, mid, nmem, nz);

    // 3) x_out = mid @ W_out + b_out  (fp16 mma, fp32 out + bias)
    gemm_h<false><<<dim3(1024 / 128, M / 128), 256, GEMM_SMEM>>>(
        1024, K, mid, wt_out, x_out, b_out);
}

// round 6
// speedup vs baseline: 4.0383x; 1.5580x over previous
#include <cuda_runtime.h>
#include <cuda_fp16.h>
#include <math.h>
#include <stdint.h>

// ---------------- scratch (no allocations allowed) ----------------
__device__ __half g_qkv_h[113246208UL];  // 36864 x 3072 (GEMM1 out, fp16)
__device__ __half g_mid_h[37748736UL];   // 36864 x 1024 (attn out, fp16, K-permuted)
__device__ __half g_x_h[37748736UL];     // x converted to fp16, K-permuted
__device__ __half g_wt_h[4194304UL];     // Wt_qkv [3072,1024] + Wt_out [1024,1024], K-permuted

__device__ __forceinline__ float sigma_fn(float x) {
    return x > 0.f ? x + 1.f : expf(x);
}
__device__ __forceinline__ void cp_async16(uint32_t saddr, const void* gptr) {
    asm volatile("cp.async.cg.shared.global [%0], [%1], 16;\n" :: "r"(saddr), "l"(gptr));
}
__device__ __forceinline__ uint32_t smem_u32(const void* p) {
    uint32_t a;
    asm("{ .reg .u64 t; cvta.to.shared.u64 t, %1; cvt.u32.u64 %0, t; }" : "=r"(a) : "l"(p));
    return a;
}

// K-interleave permutation within each 16-element group.
__host__ __device__ __forceinline__ int perm16(int j) {
    return ((j >> 1) & 3) * 4 + ((j >> 3) & 1) * 2 + (j & 1);
}
__host__ __device__ __forceinline__ int iperm16(int o) {
    return ((o >> 2) & 3) * 2 + ((o >> 1) & 1) * 8 + (o & 1);
}

// ================= fp16 mma.sync GEMM (unchanged from round 5) =================
#define GSTAGES 4
#define ROWB 96
#define STAGE_BYTES (128 * ROWB)
#define BOFF (GSTAGES * STAGE_BYTES)
#define GEMM_SMEM (2 * GSTAGES * STAGE_BYTES)

template<bool HALF_OUT>
__global__ __launch_bounds__(256, 2)
void gemm_h(int N, int K,
            const __half* __restrict__ A,
            const __half* __restrict__ Bt,
            void* __restrict__ Cout,
            const float* __restrict__ bias)
{
    extern __shared__ char smem[];
    const uint32_t sbase = smem_u32(smem);
    const int tid  = threadIdx.x;
    const int warp = tid >> 5;
    const int lane = tid & 31;
    const int g    = lane >> 2;
    const int t4   = lane & 3;
    const int wm0  = (warp & 1) * 64;
    const int wn0  = (warp >> 1) * 32;

    const size_t m0 = (size_t)blockIdx.y * 128;
    const size_t n0 = (size_t)blockIdx.x * 128;

    const int lrow = tid >> 1;
    const int lhalf = tid & 1;
    const __half* gA = A + (m0 + lrow) * K + lhalf * 16;
    const __half* gB = Bt + (n0 + lrow) * K + lhalf * 16;
    const uint32_t sArow = sbase + lrow * ROWB + lhalf * 32;
    const uint32_t sBrow = sbase + BOFF + lrow * ROWB + lhalf * 32;

    const int nchunks = K >> 5;

    float acc[4][4][4];
    #pragma unroll
    for (int i = 0; i < 4; i++)
        #pragma unroll
        for (int j = 0; j < 4; j++) {
            acc[i][j][0] = 0.f; acc[i][j][1] = 0.f;
            acc[i][j][2] = 0.f; acc[i][j][3] = 0.f;
        }

    #pragma unroll
    for (int s = 0; s < 3; s++) {
        const __half* pa = gA + s * 32;
        const __half* pb = gB + s * 32;
        uint32_t sa = sArow + s * STAGE_BYTES;
        uint32_t sb = sBrow + s * STAGE_BYTES;
        cp_async16(sa, pa);       cp_async16(sa + 16, pa + 8);
        cp_async16(sb, pb);       cp_async16(sb + 16, pb + 8);
        asm volatile("cp.async.commit_group;\n");
    }

    for (int c = 0; c < nchunks; c++) {
        asm volatile("cp.async.wait_group 2;\n");
        __syncthreads();

        const int nc = c + 3;
        if (nc < nchunks) {
            const int ns = nc & 3;
            const __half* pa = gA + nc * 32;
            const __half* pb = gB + nc * 32;
            uint32_t sa = sArow + ns * STAGE_BYTES;
            uint32_t sb = sBrow + ns * STAGE_BYTES;
            cp_async16(sa, pa);   cp_async16(sa + 16, pa + 8);
            cp_async16(sb, pb);   cp_async16(sb + 16, pb + 8);
        }
        asm volatile("cp.async.commit_group;\n");

        const int s = c & 3;
        const char* aS = smem + s * STAGE_BYTES;
        const char* bS = smem + BOFF + s * STAGE_BYTES;

        #pragma unroll
        for (int ks = 0; ks < 2; ks++) {
            uint32_t a[4][4], b[4][2];
            #pragma unroll
            for (int mt = 0; mt < 4; mt++) {
                const char* p = aS + (wm0 + mt * 16 + g) * ROWB + ks * 32 + t4 * 8;
                uint2 lo = *(const uint2*)p;
                uint2 hi = *(const uint2*)(p + 8 * ROWB);
                a[mt][0] = lo.x; a[mt][1] = hi.x; a[mt][2] = lo.y; a[mt][3] = hi.y;
            }
            #pragma unroll
            for (int nt = 0; nt < 4; nt++) {
                const char* p = bS + (wn0 + nt * 8 + g) * ROWB + ks * 32 + t4 * 8;
                uint2 bb = *(const uint2*)p;
                b[nt][0] = bb.x; b[nt][1] = bb.y;
            }
            #pragma unroll
            for (int mt = 0; mt < 4; mt++)
                #pragma unroll
                for (int nt = 0; nt < 4; nt++) {
                    asm volatile(
                        "mma.sync.aligned.m16n8k16.row.col.f32.f16.f16.f32 "
                        "{%0,%1,%2,%3}, {%4,%5,%6,%7}, {%8,%9}, {%0,%1,%2,%3};\n"
                        : "+f"(acc[mt][nt][0]), "+f"(acc[mt][nt][1]),
                          "+f"(acc[mt][nt][2]), "+f"(acc[mt][nt][3])
                        : "r"(a[mt][0]), "r"(a[mt][1]), "r"(a[mt][2]), "r"(a[mt][3]),
                          "r"(b[nt][0]), "r"(b[nt][1]));
                }
        }
    }

    #pragma unroll
    for (int mt = 0; mt < 4; mt++) {
        const size_t r0 = m0 + wm0 + mt * 16 + g;
        const size_t r1 = r0 + 8;
        #pragma unroll
        for (int nt = 0; nt < 4; nt++) {
            const int col = (int)n0 + wn0 + nt * 8 + t4 * 2;
            if (HALF_OUT) {
                __half* C = (__half*)Cout;
                *(__half2*)(C + r0 * N + col) = __floats2half2_rn(acc[mt][nt][0], acc[mt][nt][1]);
                *(__half2*)(C + r1 * N + col) = __floats2half2_rn(acc[mt][nt][2], acc[mt][nt][3]);
            } else {
                float* C = (float*)Cout;
                float b0 = bias ? bias[col] : 0.f;
                float b1 = bias ? bias[col + 1] : 0.f;
                *(float2*)(C + r0 * N + col) = make_float2(acc[mt][nt][0] + b0, acc[mt][nt][1] + b1);
                *(float2*)(C + r1 * N + col) = make_float2(acc[mt][nt][2] + b0, acc[mt][nt][3] + b1);
            }
        }
    }
}

// ---------------- preprocessing (unchanged) ----------------
__global__ __launch_bounds__(256)
void convert_x_kernel(const float* __restrict__ in, __half* __restrict__ out, int ngroups) {
    int idx = blockIdx.x * 256 + threadIdx.x;
    if (idx >= ngroups) return;
    const float* p = in + (size_t)idx * 16;
    __half h[16];
    #pragma unroll
    for (int o = 0; o < 16; o++)
        h[o] = __float2half_rn(p[iperm16(o)]);
    uint4* o4 = (uint4*)(out + (size_t)idx * 16);
    o4[0] = ((const uint4*)h)[0];
    o4[1] = ((const uint4*)h)[1];
}

__global__ __launch_bounds__(256)
void transpose_half_kernel(const float* __restrict__ in, __half* __restrict__ out,
                           int Kk, int Nn) {
    __shared__ float t[32][33];
    const int n0 = blockIdx.x * 32;
    const int k0 = blockIdx.y * 32;
    const int tx = threadIdx.x & 31;
    const int ty = threadIdx.x >> 5;
    #pragma unroll
    for (int r = 0; r < 4; r++) {
        int kr = ty + r * 8;
        t[kr][tx] = in[(size_t)(k0 + kr) * Nn + n0 + tx];
    }
    __syncthreads();
    if (threadIdx.x < 64) {
        const int nl = threadIdx.x >> 1;
        const int kg = threadIdx.x & 1;
        __half h[16];
        #pragma unroll
        for (int o = 0; o < 16; o++)
            h[o] = __float2half_rn(t[kg * 16 + iperm16(o)][nl]);
        uint4* o4 = (uint4*)(out + (size_t)(n0 + nl) * Kk + k0 + kg * 16);
        o4[0] = ((const uint4*)h)[0];
        o4[1] = ((const uint4*)h)[1];
    }
}

// ---------------- fused attention: register-tiled rewrite ----------------
#define TSEQ 32
#define DHD 64
#define P 68   // row pad for qs/ks/vs/ms (float4-aligned, conflict-free patterns)

struct AttnSmem {
    float qs[TSEQ][P];
    float ks[TSEQ][P];
    float vs[TSEQ][P];
    float ms[DHD][P];
    float sc[TSEQ][33];
    float sqT[DHD][33];   // sigma(q) transposed: sqT[dd][t]
    float skk[8][P];
    float zs[DHD];
    float denom[TSEQ];
    float ifr[DHD / 2];
};

__global__ __launch_bounds__(256)
void attn_kernel(const __half* __restrict__ qkv,
                 const float* __restrict__ mem,
                 const float* __restrict__ zin,
                 const float* __restrict__ mem_beta,
                 const float* __restrict__ inv_freq,
                 __half* __restrict__ out_mid,
                 float* __restrict__ new_mem,
                 float* __restrict__ new_z)
{
    extern __shared__ char smem_raw[];
    AttnSmem& S = *(AttnSmem*)smem_raw;

    const int bh   = blockIdx.x;
    const int s    = bh >> 4;
    const int head = bh & 15;
    const int b    = s / 576;
    const int rem  = s - b * 576;
    const int tid  = threadIdx.x;
    const int warp = tid >> 5;
    const int lane = tid & 31;
    const int row_base = b * 18432 + rem;
    const size_t mbase = (size_t)bh * (DHD * DHD);

    const float g = 1.f / (1.f + expf(-mem_beta[head]));
    const float ig = 1.f - g;

    // ---- phase 1: load qkv (half2), mem, z, inv_freq ----
    for (int e = tid; e < 1024; e += 256) {
        int t = e >> 5, d2 = (e & 31) * 2;
        size_t base = (size_t)(row_base + t * 576) * 3072 + head * 64 + d2;
        float2 q = __half22float2(*(const __half2*)(qkv + base));
        float2 k = __half22float2(*(const __half2*)(qkv + base + 1024));
        float2 v = __half22float2(*(const __half2*)(qkv + base + 2048));
        S.qs[t][d2] = q.x; S.qs[t][d2 + 1] = q.y;
        S.ks[t][d2] = k.x; S.ks[t][d2 + 1] = k.y;
        S.vs[t][d2] = v.x; S.vs[t][d2 + 1] = v.y;
    }
    for (int e = tid; e < 4096; e += 256)
        S.ms[e >> 6][e & 63] = mem[mbase + e];
    if (tid < DHD)     S.zs[tid]  = zin[(size_t)bh * DHD + tid];
    if (tid < DHD / 2) S.ifr[tid] = inv_freq[tid];
    __syncthreads();

    // ---- phase 2: skk = sigma(sigma(k_raw[:8])) ; new_z ----
    for (int e = tid; e < 8 * DHD; e += 256) {
        int t = e >> 6, i = e & 63;
        S.skk[t][i] = sigma_fn(sigma_fn(S.ks[t][i]));
    }
    if (tid < DHD) {
        float acc = S.zs[tid];
        #pragma unroll
        for (int t = 0; t < TSEQ; t++) acc += sigma_fn(S.ks[t][tid]);
        new_z[(size_t)bh * DHD + tid] = acc;
    }
    __syncthreads();

    // ---- phase 3: new_mem (coalesced) + rotary (in place) ----
    for (int e = tid; e < 4096; e += 256) {
        int i = e >> 6, j = e & 63;
        float acc = S.ms[i][j];
        #pragma unroll
        for (int t = 0; t < 8; t++) acc += S.skk[t][i] * S.vs[t][j];
        new_mem[mbase + e] = acc;
    }
    for (int e = tid; e < 1024; e += 256) {
        int t = e >> 5, j = e & 31;
        float sn, cs;
        sincosf((float)t * S.ifr[j], &sn, &cs);
        float q0 = S.qs[t][2 * j], q1 = S.qs[t][2 * j + 1];
        S.qs[t][2 * j]     = q0 * cs - q1 * sn;
        S.qs[t][2 * j + 1] = q1 * cs + q0 * sn;
        float k0 = S.ks[t][2 * j], k1 = S.ks[t][2 * j + 1];
        S.ks[t][2 * j]     = k0 * cs - k1 * sn;
        S.ks[t][2 * j + 1] = k1 * cs + k0 * sn;
    }
    __syncthreads();

    // ---- phase 4: scores (2x2 reg tile, float4 over d) + sigma_q -> sqT ----
    {
        const int tr = tid >> 4;   // 0..15
        const int tc = tid & 15;   // 0..15
        float a00 = 0.f, a01 = 0.f, a10 = 0.f, a11 = 0.f;
        #pragma unroll
        for (int d = 0; d < DHD; d += 4) {
            float4 q0 = *(const float4*)&S.qs[tr][d];
            float4 q1 = *(const float4*)&S.qs[tr + 16][d];
            float4 k0 = *(const float4*)&S.ks[tc][d];
            float4 k1 = *(const float4*)&S.ks[tc + 16][d];
            a00 += q0.x * k0.x + q0.y * k0.y + q0.z * k0.z + q0.w * k0.w;
            a01 += q0.x * k1.x + q0.y * k1.y + q0.z * k1.z + q0.w * k1.w;
            a10 += q1.x * k0.x + q1.y * k0.y + q1.z * k0.z + q1.w * k0.w;
            a11 += q1.x * k1.x + q1.y * k1.y + q1.z * k1.z + q1.w * k1.w;
        }
        S.sc[tr][tc]           = a00 * 0.125f;
        S.sc[tr][tc + 16]      = a01 * 0.125f;
        S.sc[tr + 16][tc]      = a10 * 0.125f;
        S.sc[tr + 16][tc + 16] = a11 * 0.125f;
    }
    for (int e = tid; e < 2048; e += 256) {
        int t = e >> 6, dd = e & 63;
        S.sqT[dd][t] = sigma_fn(S.qs[t][dd]);
    }
    __syncthreads();

    // ---- phase 5: warp-parallel softmax (4 rows per warp) + denom ----
    #pragma unroll
    for (int r = 0; r < 4; r++) {
        int t = warp * 4 + r;
        float v = (lane <= t) ? S.sc[t][lane] : -1e30f;
        float m = v;
        #pragma unroll
        for (int o = 16; o > 0; o >>= 1) m = fmaxf(m, __shfl_xor_sync(0xFFFFFFFFu, m, o));
        float ex = (lane <= t) ? expf(v - m) : 0.f;
        float ssum = ex;
        #pragma unroll
        for (int o = 16; o > 0; o >>= 1) ssum += __shfl_xor_sync(0xFFFFFFFFu, ssum, o);
        S.sc[t][lane] = ex / ssum;
    }
    if (tid < TSEQ) {
        float acc = 0.f;
        #pragma unroll
        for (int kx = 0; kx < DHD; kx++) acc += S.sqT[kx][tid] * S.zs[kx];
        S.denom[tid] = acc;
    }
    __syncthreads();

    // ---- phase 6: out = g*(sigma_q@mem)/denom + (1-g)*(attn@v), staged to qs ----
    {
        const int dc = warp;   // 0..7, 8-col block
        const int t  = lane;   // 0..31
        const int dd0 = dc * 8;
        float4 aA0 = {0,0,0,0}, aA1 = {0,0,0,0};
        float4 aR0 = {0,0,0,0}, aR1 = {0,0,0,0};
        #pragma unroll
        for (int tt = 0; tt < TSEQ; tt++) {
            float sv = S.sc[t][tt];
            float4 v0 = *(const float4*)&S.vs[tt][dd0];
            float4 v1 = *(const float4*)&S.vs[tt][dd0 + 4];
            aA0.x += sv * v0.x; aA0.y += sv * v0.y; aA0.z += sv * v0.z; aA0.w += sv * v0.w;
            aA1.x += sv * v1.x; aA1.y += sv * v1.y; aA1.z += sv * v1.z; aA1.w += sv * v1.w;
        }
        #pragma unroll
        for (int kx = 0; kx < DHD; kx++) {
            float sq = S.sqT[kx][t];
            float4 m0 = *(const float4*)&S.ms[kx][dd0];
            float4 m1 = *(const float4*)&S.ms[kx][dd0 + 4];
            aR0.x += sq * m0.x; aR0.y += sq * m0.y; aR0.z += sq * m0.z; aR0.w += sq * m0.w;
            aR1.x += sq * m1.x; aR1.y += sq * m1.y; aR1.z += sq * m1.z; aR1.w += sq * m1.w;
        }
        const float gi = g / S.denom[t];
        float4 o0, o1;
        o0.x = gi * aR0.x + ig * aA0.x;  o0.y = gi * aR0.y + ig * aA0.y;
        o0.z = gi * aR0.z + ig * aA0.z;  o0.w = gi * aR0.w + ig * aA0.w;
        o1.x = gi * aR1.x + ig * aA1.x;  o1.y = gi * aR1.y + ig * aA1.y;
        o1.z = gi * aR1.z + ig * aA1.z;  o1.w = gi * aR1.w + ig * aA1.w;
        *(float4*)&S.qs[t][dd0]     = o0;
        *(float4*)&S.qs[t][dd0 + 4] = o1;
    }
    __syncthreads();

    // ---- phase 7: coalesced fp16 writeback with K-permutation ----
    for (int e = tid; e < 1024; e += 256) {
        int t = e >> 5, dd = (e & 31) * 2;
        int pdd = (dd & ~15) | perm16(dd & 15);
        __half2 h = __floats2half2_rn(S.qs[t][dd], S.qs[t][dd + 1]);
        *(__half2*)(out_mid + (size_t)(row_base + t * 576) * 1024 + head * 64 + pdd) = h;
    }
}

// ---------------- launch ----------------
extern "C" void kernel_launch(void* const* d_in, const int* in_sizes, int n_in,
                              void* d_out, int out_size) {
    const float* x        = (const float*)d_in[0];
    const float* mem      = (const float*)d_in[1];
    const float* z        = (const float*)d_in[2];
    const float* W_qkv    = (const float*)d_in[3];
    const float* W_out    = (const float*)d_in[4];
    const float* b_out    = (const float*)d_in[5];
    const float* mem_beta = (const float*)d_in[6];
    const float* inv_freq = (const float*)d_in[7];

    float* x_out = (float*)d_out;
    float* nmem  = x_out + 37748736UL;
    float* nz    = x_out + 113246208UL;

    __half *qkv = nullptr, *mid = nullptr, *xh = nullptr, *wt = nullptr;
    cudaGetSymbolAddress((void**)&qkv, g_qkv_h);
    cudaGetSymbolAddress((void**)&mid, g_mid_h);
    cudaGetSymbolAddress((void**)&xh, g_x_h);
    cudaGetSymbolAddress((void**)&wt, g_wt_h);
    __half* wt_qkv = wt;
    __half* wt_out = wt + 3145728UL;

    cudaFuncSetAttribute(gemm_h<true>, cudaFuncAttributeMaxDynamicSharedMemorySize, GEMM_SMEM);
    cudaFuncSetAttribute(gemm_h<false>, cudaFuncAttributeMaxDynamicSharedMemorySize, GEMM_SMEM);
    cudaFuncSetAttribute(attn_kernel, cudaFuncAttributeMaxDynamicSharedMemorySize,
                         (int)sizeof(AttnSmem));

    const int M = 36864, K = 1024;

    convert_x_kernel<<<(M * K / 16 + 255) / 256, 256>>>(x, xh, M * K / 16);
    transpose_half_kernel<<<dim3(3072 / 32, 1024 / 32), 256>>>(W_qkv, wt_qkv, 1024, 3072);
    transpose_half_kernel<<<dim3(1024 / 32, 1024 / 32), 256>>>(W_out, wt_out, 1024, 1024);

    gemm_h<true><<<dim3(3072 / 128, M / 128), 256, GEMM_SMEM>>>(
        3072, K, xh, wt_qkv, qkv, nullptr);

    attn_kernel<<<18432, 256, sizeof(AttnSmem)>>>(
        qkv, mem, z, mem_beta, inv_freq, mid, nmem, nz);

    gemm_h<false><<<dim3(1024 / 128, M / 128), 256, GEMM_SMEM>>>(
        1024, K, mid, wt_out, x_out, b_out);
}

// round 7
// speedup vs baseline: 4.4693x; 1.1067x over previous
#include <cuda_runtime.h>
#include <cuda_fp16.h>
#include <math.h>
#include <stdint.h>

// ---------------- scratch (no allocations allowed) ----------------
__device__ __half g_qkv_h[113246208UL];  // 36864 x 3072 (GEMM1 out, fp16)
__device__ __half g_mid_h[37748736UL];   // 36864 x 1024 (attn out, fp16, K-permuted)
__device__ __half g_x_h[37748736UL];     // x converted to fp16, K-permuted
__device__ __half g_wt_h[4194304UL];     // Wt_qkv [3072,1024] + Wt_out [1024,1024], K-permuted
__device__ float2 g_rope[1024];          // cos/sin(t * inv_freq[j]), t,j in [0,32)

__device__ __forceinline__ float sigma_fn(float x) {
    return x > 0.f ? x + 1.f : __expf(x);
}
__device__ __forceinline__ void cp_async16(uint32_t saddr, const void* gptr) {
    asm volatile("cp.async.cg.shared.global [%0], [%1], 16;\n" :: "r"(saddr), "l"(gptr));
}
__device__ __forceinline__ uint32_t smem_u32(const void* p) {
    uint32_t a;
    asm("{ .reg .u64 t; cvta.to.shared.u64 t, %1; cvt.u32.u64 %0, t; }" : "=r"(a) : "l"(p));
    return a;
}

// K-interleave permutation within each 16-element group.
__host__ __device__ __forceinline__ int perm16(int j) {
    return ((j >> 1) & 3) * 4 + ((j >> 3) & 1) * 2 + (j & 1);
}
__host__ __device__ __forceinline__ int iperm16(int o) {
    return ((o >> 2) & 3) * 2 + ((o >> 1) & 1) * 8 + (o & 1);
}

// ================= fp16 mma.sync GEMM, 128x256 CTA tile =================
// C[M,N] = A[M,K] @ Bt[N,K]^T (+bias). A, Bt fp16 with K-permuted columns.
// BK=32 halves/stage, 3-stage cp.async ring, 8 warps of 64x64, m16n8k16.
#define ROWB 96
#define A_STAGE (128 * ROWB)             // 12288
#define B_STAGE (256 * ROWB)             // 24576
#define B_BASE  (3 * A_STAGE)            // 36864
#define GEMM_SMEM (3 * (A_STAGE + B_STAGE))  // 110592

template<bool HALF_OUT>
__global__ __launch_bounds__(256, 1)
void gemm_h(int N, int K,
            const __half* __restrict__ A,
            const __half* __restrict__ Bt,
            void* __restrict__ Cout,
            const float* __restrict__ bias)
{
    extern __shared__ char smem[];
    const uint32_t sbase = smem_u32(smem);
    const int tid  = threadIdx.x;
    const int warp = tid >> 5;
    const int lane = tid & 31;
    const int g    = lane >> 2;
    const int t4   = lane & 3;
    const int wm0  = (warp & 1) * 64;
    const int wn0  = (warp >> 1) * 64;

    const size_t m0 = (size_t)blockIdx.y * 128;
    const size_t n0 = (size_t)blockIdx.x * 256;

    // loader: 1536 16B-chunks per stage (A:512, B:1024) -> 6 per thread
    const __half* gp[6];
    uint32_t sOff[6], sStride[6];
    #pragma unroll
    for (int u = 0; u < 6; u++) {
        int c16 = tid + u * 256;
        bool isA = c16 < 512;
        int row  = isA ? (c16 >> 2) : ((c16 - 512) >> 2);
        int colh = (c16 & 3) * 8;   // halves
        gp[u] = (isA ? (A + (m0 + row) * K) : (Bt + (n0 + row) * K)) + colh;
        sOff[u] = (isA ? 0u : (uint32_t)B_BASE) + row * ROWB + colh * 2;
        sStride[u] = isA ? (uint32_t)A_STAGE : (uint32_t)B_STAGE;
    }

    const int nchunks = K >> 5;   // 32

    float acc[4][8][4];
    #pragma unroll
    for (int i = 0; i < 4; i++)
        #pragma unroll
        for (int j = 0; j < 8; j++)
            #pragma unroll
            for (int r = 0; r < 4; r++) acc[i][j][r] = 0.f;

    // prologue: stages 0,1
    #pragma unroll
    for (int s = 0; s < 2; s++) {
        #pragma unroll
        for (int u = 0; u < 6; u++)
            cp_async16(sbase + sOff[u] + s * sStride[u], gp[u] + s * 32);
        asm volatile("cp.async.commit_group;\n");
    }

    for (int c = 0; c < nchunks; c++) {
        asm volatile("cp.async.wait_group 1;\n");
        __syncthreads();

        const int nc = c + 2;
        if (nc < nchunks) {
            const int ns = nc % 3;
            #pragma unroll
            for (int u = 0; u < 6; u++)
                cp_async16(sbase + sOff[u] + ns * sStride[u], gp[u] + nc * 32);
        }
        asm volatile("cp.async.commit_group;\n");

        const int s = c % 3;
        const char* aS = smem + s * A_STAGE;
        const char* bS = smem + B_BASE + s * B_STAGE;

        #pragma unroll
        for (int ks = 0; ks < 2; ks++) {
            uint32_t a[4][4], b[8][2];
            #pragma unroll
            for (int mt = 0; mt < 4; mt++) {
                const char* p = aS + (wm0 + mt * 16 + g) * ROWB + ks * 32 + t4 * 8;
                uint2 lo = *(const uint2*)p;
                uint2 hi = *(const uint2*)(p + 8 * ROWB);
                a[mt][0] = lo.x; a[mt][1] = hi.x; a[mt][2] = lo.y; a[mt][3] = hi.y;
            }
            #pragma unroll
            for (int nt = 0; nt < 8; nt++) {
                const char* p = bS + (wn0 + nt * 8 + g) * ROWB + ks * 32 + t4 * 8;
                uint2 bb = *(const uint2*)p;
                b[nt][0] = bb.x; b[nt][1] = bb.y;
            }
            #pragma unroll
            for (int mt = 0; mt < 4; mt++)
                #pragma unroll
                for (int nt = 0; nt < 8; nt++) {
                    asm volatile(
                        "mma.sync.aligned.m16n8k16.row.col.f32.f16.f16.f32 "
                        "{%0,%1,%2,%3}, {%4,%5,%6,%7}, {%8,%9}, {%0,%1,%2,%3};\n"
                        : "+f"(acc[mt][nt][0]), "+f"(acc[mt][nt][1]),
                          "+f"(acc[mt][nt][2]), "+f"(acc[mt][nt][3])
                        : "r"(a[mt][0]), "r"(a[mt][1]), "r"(a[mt][2]), "r"(a[mt][3]),
                          "r"(b[nt][0]), "r"(b[nt][1]));
                }
        }
    }

    // ---- epilogue ----
    #pragma unroll
    for (int mt = 0; mt < 4; mt++) {
        const size_t r0 = m0 + wm0 + mt * 16 + g;
        const size_t r1 = r0 + 8;
        #pragma unroll
        for (int nt = 0; nt < 8; nt++) {
            const int col = (int)n0 + wn0 + nt * 8 + t4 * 2;
            if (HALF_OUT) {
                __half* C = (__half*)Cout;
                *(__half2*)(C + r0 * N + col) = __floats2half2_rn(acc[mt][nt][0], acc[mt][nt][1]);
                *(__half2*)(C + r1 * N + col) = __floats2half2_rn(acc[mt][nt][2], acc[mt][nt][3]);
            } else {
                float* C = (float*)Cout;
                float b0 = bias ? bias[col] : 0.f;
                float b1 = bias ? bias[col + 1] : 0.f;
                *(float2*)(C + r0 * N + col) = make_float2(acc[mt][nt][0] + b0, acc[mt][nt][1] + b1);
                *(float2*)(C + r1 * N + col) = make_float2(acc[mt][nt][2] + b0, acc[mt][nt][3] + b1);
            }
        }
    }
}

// ---------------- preprocessing ----------------
__global__ __launch_bounds__(256)
void convert_x_kernel(const float* __restrict__ in, __half* __restrict__ out, int ngroups) {
    int idx = blockIdx.x * 256 + threadIdx.x;
    if (idx >= ngroups) return;
    const float* p = in + (size_t)idx * 16;
    __half h[16];
    #pragma unroll
    for (int o = 0; o < 16; o++)
        h[o] = __float2half_rn(p[iperm16(o)]);
    uint4* o4 = (uint4*)(out + (size_t)idx * 16);
    o4[0] = ((const uint4*)h)[0];
    o4[1] = ((const uint4*)h)[1];
}

__global__ __launch_bounds__(256)
void transpose_half_kernel(const float* __restrict__ in, __half* __restrict__ out,
                           int Kk, int Nn) {
    __shared__ float t[32][33];
    const int n0 = blockIdx.x * 32;
    const int k0 = blockIdx.y * 32;
    const int tx = threadIdx.x & 31;
    const int ty = threadIdx.x >> 5;
    #pragma unroll
    for (int r = 0; r < 4; r++) {
        int kr = ty + r * 8;
        t[kr][tx] = in[(size_t)(k0 + kr) * Nn + n0 + tx];
    }
    __syncthreads();
    if (threadIdx.x < 64) {
        const int nl = threadIdx.x >> 1;
        const int kg = threadIdx.x & 1;
        __half h[16];
        #pragma unroll
        for (int o = 0; o < 16; o++)
            h[o] = __float2half_rn(t[kg * 16 + iperm16(o)][nl]);
        uint4* o4 = (uint4*)(out + (size_t)(n0 + nl) * Kk + k0 + kg * 16);
        o4[0] = ((const uint4*)h)[0];
        o4[1] = ((const uint4*)h)[1];
    }
}

// rope table: cos/sin(t * inv_freq[j]) for t,j in [0,32)
__global__ void rope_table_kernel(const float* __restrict__ inv_freq,
                                  float2* __restrict__ tab) {
    int t = threadIdx.x >> 5, j = threadIdx.x & 31;
    float sn, cs;
    sincosf((float)t * inv_freq[j], &sn, &cs);
    tab[t * 32 + j] = make_float2(cs, sn);
}

// ---------------- fused attention ----------------
#define TSEQ 32
#define DHD 64
#define P 68

struct AttnSmem {
    float qs[TSEQ][P];
    float ks[TSEQ][P];
    float vs[TSEQ][P];
    float ms[DHD][P];
    float sc[TSEQ][33];
    float sqT[DHD][33];
    float skk[8][P];
    float2 rope[TSEQ][32];
    float zs[DHD];
    float denom[TSEQ];
};

__global__ __launch_bounds__(256)
void attn_kernel(const __half* __restrict__ qkv,
                 const float* __restrict__ mem,
                 const float* __restrict__ zin,
                 const float* __restrict__ mem_beta,
                 const float2* __restrict__ rope_tab,
                 __half* __restrict__ out_mid,
                 float* __restrict__ new_mem,
                 float* __restrict__ new_z)
{
    extern __shared__ char smem_raw[];
    AttnSmem& S = *(AttnSmem*)smem_raw;

    const int bh   = blockIdx.x;
    const int s    = bh >> 4;
    const int head = bh & 15;
    const int b    = s / 576;
    const int rem  = s - b * 576;
    const int tid  = threadIdx.x;
    const int warp = tid >> 5;
    const int lane = tid & 31;
    const int row_base = b * 18432 + rem;
    const size_t mbase = (size_t)bh * (DHD * DHD);

    const float g = 1.f / (1.f + __expf(-mem_beta[head]));
    const float ig = 1.f - g;

    // ---- phase 1: load qkv (half2), mem, z, rope table ----
    for (int e = tid; e < 1024; e += 256) {
        int t = e >> 5, d2 = (e & 31) * 2;
        size_t base = (size_t)(row_base + t * 576) * 3072 + head * 64 + d2;
        float2 q = __half22float2(*(const __half2*)(qkv + base));
        float2 k = __half22float2(*(const __half2*)(qkv + base + 1024));
        float2 v = __half22float2(*(const __half2*)(qkv + base + 2048));
        S.qs[t][d2] = q.x; S.qs[t][d2 + 1] = q.y;
        S.ks[t][d2] = k.x; S.ks[t][d2 + 1] = k.y;
        S.vs[t][d2] = v.x; S.vs[t][d2 + 1] = v.y;
        ((float2*)S.rope)[e] = rope_tab[e];
    }
    for (int e = tid; e < 4096; e += 256)
        S.ms[e >> 6][e & 63] = mem[mbase + e];
    if (tid < DHD) S.zs[tid] = zin[(size_t)bh * DHD + tid];
    __syncthreads();

    // ---- phase 2: skk = sigma(sigma(k_raw[:8])) ; new_z ----
    for (int e = tid; e < 8 * DHD; e += 256) {
        int t = e >> 6, i = e & 63;
        S.skk[t][i] = sigma_fn(sigma_fn(S.ks[t][i]));
    }
    if (tid < DHD) {
        float acc = S.zs[tid];
        #pragma unroll
        for (int t = 0; t < TSEQ; t++) acc += sigma_fn(S.ks[t][tid]);
        new_z[(size_t)bh * DHD + tid] = acc;
    }
    __syncthreads();

    // ---- phase 3: new_mem (coalesced) + rotary (table-driven) ----
    for (int e = tid; e < 4096; e += 256) {
        int i = e >> 6, j = e & 63;
        float acc = S.ms[i][j];
        #pragma unroll
        for (int t = 0; t < 8; t++) acc += S.skk[t][i] * S.vs[t][j];
        new_mem[mbase + e] = acc;
    }
    for (int e = tid; e < 1024; e += 256) {
        int t = e >> 5, j = e & 31;
        float2 cssn = S.rope[t][j];
        float q0 = S.qs[t][2 * j], q1 = S.qs[t][2 * j + 1];
        S.qs[t][2 * j]     = q0 * cssn.x - q1 * cssn.y;
        S.qs[t][2 * j + 1] = q1 * cssn.x + q0 * cssn.y;
        float k0 = S.ks[t][2 * j], k1 = S.ks[t][2 * j + 1];
        S.ks[t][2 * j]     = k0 * cssn.x - k1 * cssn.y;
        S.ks[t][2 * j + 1] = k1 * cssn.x + k0 * cssn.y;
    }
    __syncthreads();

    // ---- phase 4: scores (2x2 reg tile, float4 over d) + sigma_q -> sqT ----
    {
        const int tr = tid >> 4;
        const int tc = tid & 15;
        float a00 = 0.f, a01 = 0.f, a10 = 0.f, a11 = 0.f;
        #pragma unroll
        for (int d = 0; d < DHD; d += 4) {
            float4 q0 = *(const float4*)&S.qs[tr][d];
            float4 q1 = *(const float4*)&S.qs[tr + 16][d];
            float4 k0 = *(const float4*)&S.ks[tc][d];
            float4 k1 = *(const float4*)&S.ks[tc + 16][d];
            a00 += q0.x * k0.x + q0.y * k0.y + q0.z * k0.z + q0.w * k0.w;
            a01 += q0.x * k1.x + q0.y * k1.y + q0.z * k1.z + q0.w * k1.w;
            a10 += q1.x * k0.x + q1.y * k0.y + q1.z * k0.z + q1.w * k0.w;
            a11 += q1.x * k1.x + q1.y * k1.y + q1.z * k1.z + q1.w * k1.w;
        }
        S.sc[tr][tc]           = a00 * 0.125f;
        S.sc[tr][tc + 16]      = a01 * 0.125f;
        S.sc[tr + 16][tc]      = a10 * 0.125f;
        S.sc[tr + 16][tc + 16] = a11 * 0.125f;
    }
    for (int e = tid; e < 2048; e += 256) {
        int t = e >> 6, dd = e & 63;
        S.sqT[dd][t] = sigma_fn(S.qs[t][dd]);
    }
    __syncthreads();

    // ---- phase 5: warp-parallel softmax + denom ----
    #pragma unroll
    for (int r = 0; r < 4; r++) {
        int t = warp * 4 + r;
        float v = (lane <= t) ? S.sc[t][lane] : -1e30f;
        float m = v;
        #pragma unroll
        for (int o = 16; o > 0; o >>= 1) m = fmaxf(m, __shfl_xor_sync(0xFFFFFFFFu, m, o));
        float ex = (lane <= t) ? __expf(v - m) : 0.f;
        float ssum = ex;
        #pragma unroll
        for (int o = 16; o > 0; o >>= 1) ssum += __shfl_xor_sync(0xFFFFFFFFu, ssum, o);
        S.sc[t][lane] = ex / ssum;
    }
    if (tid < TSEQ) {
        float acc = 0.f;
        #pragma unroll
        for (int kx = 0; kx < DHD; kx++) acc += S.sqT[kx][tid] * S.zs[kx];
        S.denom[tid] = acc;
    }
    __syncthreads();

    // ---- phase 6: out = g*(sigma_q@mem)/denom + (1-g)*(attn@v) ----
    {
        const int dc = warp;
        const int t  = lane;
        const int dd0 = dc * 8;
        float4 aA0 = {0,0,0,0}, aA1 = {0,0,0,0};
        float4 aR0 = {0,0,0,0}, aR1 = {0,0,0,0};
        #pragma unroll
        for (int tt = 0; tt < TSEQ; tt++) {
            float sv = S.sc[t][tt];
            float4 v0 = *(const float4*)&S.vs[tt][dd0];
            float4 v1 = *(const float4*)&S.vs[tt][dd0 + 4];
            aA0.x += sv * v0.x; aA0.y += sv * v0.y; aA0.z += sv * v0.z; aA0.w += sv * v0.w;
            aA1.x += sv * v1.x; aA1.y += sv * v1.y; aA1.z += sv * v1.z; aA1.w += sv * v1.w;
        }
        #pragma unroll
        for (int kx = 0; kx < DHD; kx++) {
            float sq = S.sqT[kx][t];
            float4 m0 = *(const float4*)&S.ms[kx][dd0];
            float4 m1 = *(const float4*)&S.ms[kx][dd0 + 4];
            aR0.x += sq * m0.x; aR0.y += sq * m0.y; aR0.z += sq * m0.z; aR0.w += sq * m0.w;
            aR1.x += sq * m1.x; aR1.y += sq * m1.y; aR1.z += sq * m1.z; aR1.w += sq * m1.w;
        }
        const float gi = g / S.denom[t];
        float4 o0, o1;
        o0.x = gi * aR0.x + ig * aA0.x;  o0.y = gi * aR0.y + ig * aA0.y;
        o0.z = gi * aR0.z + ig * aA0.z;  o0.w = gi * aR0.w + ig * aA0.w;
        o1.x = gi * aR1.x + ig * aA1.x;  o1.y = gi * aR1.y + ig * aA1.y;
        o1.z = gi * aR1.z + ig * aA1.z;  o1.w = gi * aR1.w + ig * aA1.w;
        *(float4*)&S.qs[t][dd0]     = o0;
        *(float4*)&S.qs[t][dd0 + 4] = o1;
    }
    __syncthreads();

    // ---- phase 7: coalesced fp16 writeback with K-permutation ----
    for (int e = tid; e < 1024; e += 256) {
        int t = e >> 5, dd = (e & 31) * 2;
        int pdd = (dd & ~15) | perm16(dd & 15);
        __half2 h = __floats2half2_rn(S.qs[t][dd], S.qs[t][dd + 1]);
        *(__half2*)(out_mid + (size_t)(row_base + t * 576) * 1024 + head * 64 + pdd) = h;
    }
}

// ---------------- launch ----------------
extern "C" void kernel_launch(void* const* d_in, const int* in_sizes, int n_in,
                              void* d_out, int out_size) {
    const float* x        = (const float*)d_in[0];
    const float* mem      = (const float*)d_in[1];
    const float* z        = (const float*)d_in[2];
    const float* W_qkv    = (const float*)d_in[3];
    const float* W_out    = (const float*)d_in[4];
    const float* b_out    = (const float*)d_in[5];
    const float* mem_beta = (const float*)d_in[6];
    const float* inv_freq = (const float*)d_in[7];

    float* x_out = (float*)d_out;
    float* nmem  = x_out + 37748736UL;
    float* nz    = x_out + 113246208UL;

    __half *qkv = nullptr, *mid = nullptr, *xh = nullptr, *wt = nullptr;
    float2* rope = nullptr;
    cudaGetSymbolAddress((void**)&qkv, g_qkv_h);
    cudaGetSymbolAddress((void**)&mid, g_mid_h);
    cudaGetSymbolAddress((void**)&xh, g_x_h);
    cudaGetSymbolAddress((void**)&wt, g_wt_h);
    cudaGetSymbolAddress((void**)&rope, g_rope);
    __half* wt_qkv = wt;
    __half* wt_out = wt + 3145728UL;

    cudaFuncSetAttribute(gemm_h<true>, cudaFuncAttributeMaxDynamicSharedMemorySize, GEMM_SMEM);
    cudaFuncSetAttribute(gemm_h<false>, cudaFuncAttributeMaxDynamicSharedMemorySize, GEMM_SMEM);
    cudaFuncSetAttribute(attn_kernel, cudaFuncAttributeMaxDynamicSharedMemorySize,
                         (int)sizeof(AttnSmem));

    const int M = 36864, K = 1024;

    convert_x_kernel<<<(M * K / 16 + 255) / 256, 256>>>(x, xh, M * K / 16);
    transpose_half_kernel<<<dim3(3072 / 32, 1024 / 32), 256>>>(W_qkv, wt_qkv, 1024, 3072);
    transpose_half_kernel<<<dim3(1024 / 32, 1024 / 32), 256>>>(W_out, wt_out, 1024, 1024);
    rope_table_kernel<<<1, 1024>>>(inv_freq, rope);

    gemm_h<true><<<dim3(3072 / 256, M / 128), 256, GEMM_SMEM>>>(
        3072, K, xh, wt_qkv, qkv, nullptr);

    attn_kernel<<<18432, 256, sizeof(AttnSmem)>>>(
        qkv, mem, z, mem_beta, rope, mid, nmem, nz);

    gemm_h<false><<<dim3(1024 / 256, M / 128), 256, GEMM_SMEM>>>(
        1024, K, mid, wt_out, x_out, b_out);
}

// round 9
// speedup vs baseline: 4.9133x; 1.0993x over previous
#include <cuda_runtime.h>
#include <cuda_fp16.h>
#include <math.h>
#include <stdint.h>

// ---------------- scratch (no allocations allowed) ----------------
__device__ __half g_qkv_h[113246208UL];  // 36864 x 3072 (GEMM1 out, fp16)
__device__ __half g_mid_h[37748736UL];   // 36864 x 1024 (attn out, fp16)
__device__ __half g_x_h[37748736UL];     // x converted to fp16
__device__ __half g_wt_h[4194304UL];     // Wt_qkv [3072,1024] + Wt_out [1024,1024]
__device__ float2 g_rope[1024];          // cos/sin(t * inv_freq[j])

__device__ __forceinline__ float sigma_fn(float x) {
    return x > 0.f ? x + 1.f : __expf(x);
}
__device__ __forceinline__ void cp_async16(uint32_t saddr, const void* gptr) {
    asm volatile("cp.async.cg.shared.global [%0], [%1], 16;\n" :: "r"(saddr), "l"(gptr));
}
__device__ __forceinline__ uint32_t smem_u32(const void* p) {
    uint32_t a;
    asm("{ .reg .u64 t; cvta.to.shared.u64 t, %1; cvt.u32.u64 %0, t; }" : "=r"(a) : "l"(p));
    return a;
}
#define LDSM4(r0, r1, r2, r3, addr) \
    asm volatile("ldmatrix.sync.aligned.m8n8.x4.shared.b16 {%0,%1,%2,%3}, [%4];" \
                 : "=r"(r0), "=r"(r1), "=r"(r2), "=r"(r3) : "r"(addr))

// ================= fp16 mma.sync GEMM, ldmatrix + SW128 =================
// C[M,N] = A[M,K] @ Bt[N,K]^T (+bias). Plain K-major fp16 operands.
// 128x128 tile, BK=64 halves (128B rows, SW128 swizzle), 3-stage cp.async,
// 8 warps of 64x32, fragments via ldmatrix.x4.
#define A_ST 16384               // A stage: 128 rows x 128B
#define STG  32768               // full stage (A+B)
#define NST  3
#define GEMM_SMEM (NST * STG)    // 98304

template<bool HALF_OUT>
__global__ __launch_bounds__(256, 2)
void gemm_h(int N, int K,
            const __half* __restrict__ A,
            const __half* __restrict__ Bt,
            void* __restrict__ Cout,
            const float* __restrict__ bias)
{
    extern __shared__ char smem[];
    const uint32_t sbase = smem_u32(smem);
    const int tid  = threadIdx.x;
    const int warp = tid >> 5;
    const int lane = tid & 31;
    const int g    = lane >> 2;
    const int t4   = lane & 3;
    const int wm0  = (warp & 1) * 64;
    const int wn0  = (warp >> 1) * 32;

    const size_t m0 = (size_t)blockIdx.y * 128;
    const size_t n0 = (size_t)blockIdx.x * 128;

    // ---- loader: thread handles rows lrow+u*32 (u=0..3) for A and B, chunk lc8 ----
    const int lrow = tid >> 3;        // 0..31
    const int lc8  = tid & 7;         // 16B chunk within 128B row
    const __half* gA = A  + (m0 + lrow) * K + lc8 * 8;
    const __half* gB = Bt + (n0 + lrow) * K + lc8 * 8;
    // swizzled store offset: chunk position = lc8 ^ (row & 7); row&7 invariant under +32
    const uint32_t stA = lrow * 128 + ((lc8 ^ (lrow & 7)) << 4);
    const uint32_t stB = stA + A_ST;

    // ---- fragment base offsets (XOR-swizzled); per-ks address = base ^ (ks<<5) ----
    uint32_t abase[4], bbase[2];
    {
        const uint32_t sw = (((lane >> 4) ^ (lane & 7)) << 4);
        #pragma unroll
        for (int mt = 0; mt < 4; mt++)
            abase[mt] = (wm0 + mt * 16 + (lane & 15)) * 128 + sw;
        #pragma unroll
        for (int p = 0; p < 2; p++)
            bbase[p] = A_ST + (wn0 + p * 16 + (lane & 15)) * 128 + sw;
    }

    const int nch = K >> 6;   // chunks of 64 halves

    float acc[4][4][4];
    #pragma unroll
    for (int i = 0; i < 4; i++)
        #pragma unroll
        for (int j = 0; j < 4; j++)
            #pragma unroll
            for (int r = 0; r < 4; r++) acc[i][j][r] = 0.f;

    // ---- prologue: stages 0,1 ----
    #pragma unroll
    for (int s = 0; s < 2; s++) {
        #pragma unroll
        for (int u = 0; u < 4; u++) {
            cp_async16(sbase + stA + s * STG + u * 4096, gA + (size_t)u * 32 * K + s * 64);
            cp_async16(sbase + stB + s * STG + u * 4096, gB + (size_t)u * 32 * K + s * 64);
        }
        asm volatile("cp.async.commit_group;\n");
    }

    for (int c = 0; c < nch; c++) {
        asm volatile("cp.async.wait_group 1;\n");
        __syncthreads();

        const int nc = c + 2;
        if (nc < nch) {
            const int ns = nc % 3;
            #pragma unroll
            for (int u = 0; u < 4; u++) {
                cp_async16(sbase + stA + ns * STG + u * 4096, gA + (size_t)u * 32 * K + nc * 64);
                cp_async16(sbase + stB + ns * STG + u * 4096, gB + (size_t)u * 32 * K + nc * 64);
            }
        }
        asm volatile("cp.async.commit_group;\n");

        const uint32_t so = sbase + (c % 3) * STG;

        #pragma unroll
        for (int ks = 0; ks < 4; ks++) {
            const uint32_t kx = (uint32_t)ks << 5;
            uint32_t a[4][4], b[4][2];
            #pragma unroll
            for (int mt = 0; mt < 4; mt++)
                LDSM4(a[mt][0], a[mt][1], a[mt][2], a[mt][3], so + (abase[mt] ^ kx));
            #pragma unroll
            for (int p = 0; p < 2; p++)
                LDSM4(b[2 * p][0], b[2 * p + 1][0], b[2 * p][1], b[2 * p + 1][1],
                      so + (bbase[p] ^ kx));
            #pragma unroll
            for (int mt = 0; mt < 4; mt++)
                #pragma unroll
                for (int nt = 0; nt < 4; nt++) {
                    asm volatile(
                        "mma.sync.aligned.m16n8k16.row.col.f32.f16.f16.f32 "
                        "{%0,%1,%2,%3}, {%4,%5,%6,%7}, {%8,%9}, {%0,%1,%2,%3};\n"
                        : "+f"(acc[mt][nt][0]), "+f"(acc[mt][nt][1]),
                          "+f"(acc[mt][nt][2]), "+f"(acc[mt][nt][3])
                        : "r"(a[mt][0]), "r"(a[mt][1]), "r"(a[mt][2]), "r"(a[mt][3]),
                          "r"(b[nt][0]), "r"(b[nt][1]));
                }
        }
    }

    // ---- epilogue ----
    #pragma unroll
    for (int mt = 0; mt < 4; mt++) {
        const size_t r0 = m0 + wm0 + mt * 16 + g;
        const size_t r1 = r0 + 8;
        #pragma unroll
        for (int nt = 0; nt < 4; nt++) {
            const int col = (int)n0 + wn0 + nt * 8 + t4 * 2;
            if (HALF_OUT) {
                __half* C = (__half*)Cout;
                *(__half2*)(C + r0 * N + col) = __floats2half2_rn(acc[mt][nt][0], acc[mt][nt][1]);
                *(__half2*)(C + r1 * N + col) = __floats2half2_rn(acc[mt][nt][2], acc[mt][nt][3]);
            } else {
                float* C = (float*)Cout;
                float b0 = bias ? bias[col] : 0.f;
                float b1 = bias ? bias[col + 1] : 0.f;
                *(float2*)(C + r0 * N + col) = make_float2(acc[mt][nt][0] + b0, acc[mt][nt][1] + b1);
                *(float2*)(C + r1 * N + col) = make_float2(acc[mt][nt][2] + b0, acc[mt][nt][3] + b1);
            }
        }
    }
}

// ---------------- preprocessing (no permutation) ----------------
__global__ __launch_bounds__(256)
void convert_x_kernel(const float4* __restrict__ in, uint4* __restrict__ out, int n8) {
    int i = blockIdx.x * 256 + threadIdx.x;
    if (i >= n8) return;
    float4 f0 = in[2 * i], f1 = in[2 * i + 1];
    __half2 h[4];
    h[0] = __floats2half2_rn(f0.x, f0.y);
    h[1] = __floats2half2_rn(f0.z, f0.w);
    h[2] = __floats2half2_rn(f1.x, f1.y);
    h[3] = __floats2half2_rn(f1.z, f1.w);
    out[i] = *(const uint4*)h;
}

__global__ __launch_bounds__(256)
void transpose_half_kernel(const float* __restrict__ in, __half* __restrict__ out,
                           int Kk, int Nn) {
    __shared__ float t[32][33];
    const int n0 = blockIdx.x * 32;
    const int k0 = blockIdx.y * 32;
    const int tx = threadIdx.x & 31;
    const int ty = threadIdx.x >> 5;
    #pragma unroll
    for (int r = 0; r < 4; r++) {
        int kr = ty + r * 8;
        t[kr][tx] = in[(size_t)(k0 + kr) * Nn + n0 + tx];
    }
    __syncthreads();
    if (threadIdx.x < 64) {
        const int nl = threadIdx.x >> 1;
        const int kg = threadIdx.x & 1;
        __half h[16];
        #pragma unroll
        for (int o = 0; o < 16; o++)
            h[o] = __float2half_rn(t[kg * 16 + o][nl]);
        uint4* o4 = (uint4*)(out + (size_t)(n0 + nl) * Kk + k0 + kg * 16);
        o4[0] = ((const uint4*)h)[0];
        o4[1] = ((const uint4*)h)[1];
    }
}

__global__ void rope_table_kernel(const float* __restrict__ inv_freq,
                                  float2* __restrict__ tab) {
    int t = threadIdx.x >> 5, j = threadIdx.x & 31;
    float sn, cs;
    sincosf((float)t * inv_freq[j], &sn, &cs);
    tab[t * 32 + j] = make_float2(cs, sn);
}

// ---------------- fused attention (round-7 passing version, plain writeback) ----
#define TSEQ 32
#define DHD 64
#define P 68

struct AttnSmem {
    float qs[TSEQ][P];
    float ks[TSEQ][P];
    float vs[TSEQ][P];
    float ms[DHD][P];
    float sc[TSEQ][33];
    float sqT[DHD][33];
    float skk[8][P];
    float2 rope[TSEQ][32];
    float zs[DHD];
    float denom[TSEQ];
};

__global__ __launch_bounds__(256)
void attn_kernel(const __half* __restrict__ qkv,
                 const float* __restrict__ mem,
                 const float* __restrict__ zin,
                 const float* __restrict__ mem_beta,
                 const float2* __restrict__ rope_tab,
                 __half* __restrict__ out_mid,
                 float* __restrict__ new_mem,
                 float* __restrict__ new_z)
{
    extern __shared__ char smem_raw[];
    AttnSmem& S = *(AttnSmem*)smem_raw;

    const int bh   = blockIdx.x;
    const int s    = bh >> 4;
    const int head = bh & 15;
    const int b    = s / 576;
    const int rem  = s - b * 576;
    const int tid  = threadIdx.x;
    const int warp = tid >> 5;
    const int lane = tid & 31;
    const int row_base = b * 18432 + rem;
    const size_t mbase = (size_t)bh * (DHD * DHD);

    const float g = 1.f / (1.f + __expf(-mem_beta[head]));
    const float ig = 1.f - g;

    // ---- phase 1: load qkv (half2), mem, z, rope table ----
    for (int e = tid; e < 1024; e += 256) {
        int t = e >> 5, d2 = (e & 31) * 2;
        size_t base = (size_t)(row_base + t * 576) * 3072 + head * 64 + d2;
        float2 q = __half22float2(*(const __half2*)(qkv + base));
        float2 k = __half22float2(*(const __half2*)(qkv + base + 1024));
        float2 v = __half22float2(*(const __half2*)(qkv + base + 2048));
        S.qs[t][d2] = q.x; S.qs[t][d2 + 1] = q.y;
        S.ks[t][d2] = k.x; S.ks[t][d2 + 1] = k.y;
        S.vs[t][d2] = v.x; S.vs[t][d2 + 1] = v.y;
        ((float2*)S.rope)[e] = rope_tab[e];
    }
    for (int e = tid; e < 4096; e += 256)
        S.ms[e >> 6][e & 63] = mem[mbase + e];
    if (tid < DHD) S.zs[tid] = zin[(size_t)bh * DHD + tid];
    __syncthreads();

    // ---- phase 2: skk = sigma(sigma(k_raw[:8])) ; new_z ----
    for (int e = tid; e < 8 * DHD; e += 256) {
        int t = e >> 6, i = e & 63;
        S.skk[t][i] = sigma_fn(sigma_fn(S.ks[t][i]));
    }
    if (tid < DHD) {
        float acc = S.zs[tid];
        #pragma unroll
        for (int t = 0; t < TSEQ; t++) acc += sigma_fn(S.ks[t][tid]);
        new_z[(size_t)bh * DHD + tid] = acc;
    }
    __syncthreads();

    // ---- phase 3: new_mem + rotary ----
    for (int e = tid; e < 4096; e += 256) {
        int i = e >> 6, j = e & 63;
        float acc = S.ms[i][j];
        #pragma unroll
        for (int t = 0; t < 8; t++) acc += S.skk[t][i] * S.vs[t][j];
        new_mem[mbase + e] = acc;
    }
    for (int e = tid; e < 1024; e += 256) {
        int t = e >> 5, j = e & 31;
        float2 cssn = S.rope[t][j];
        float q0 = S.qs[t][2 * j], q1 = S.qs[t][2 * j + 1];
        S.qs[t][2 * j]     = q0 * cssn.x - q1 * cssn.y;
        S.qs[t][2 * j + 1] = q1 * cssn.x + q0 * cssn.y;
        float k0 = S.ks[t][2 * j], k1 = S.ks[t][2 * j + 1];
        S.ks[t][2 * j]     = k0 * cssn.x - k1 * cssn.y;
        S.ks[t][2 * j + 1] = k1 * cssn.x + k0 * cssn.y;
    }
    __syncthreads();

    // ---- phase 4: scores + sigma_q -> sqT ----
    {
        const int tr = tid >> 4;
        const int tc = tid & 15;
        float a00 = 0.f, a01 = 0.f, a10 = 0.f, a11 = 0.f;
        #pragma unroll
        for (int d = 0; d < DHD; d += 4) {
            float4 q0 = *(const float4*)&S.qs[tr][d];
            float4 q1 = *(const float4*)&S.qs[tr + 16][d];
            float4 k0 = *(const float4*)&S.ks[tc][d];
            float4 k1 = *(const float4*)&S.ks[tc + 16][d];
            a00 += q0.x * k0.x + q0.y * k0.y + q0.z * k0.z + q0.w * k0.w;
            a01 += q0.x * k1.x + q0.y * k1.y + q0.z * k1.z + q0.w * k1.w;
            a10 += q1.x * k0.x + q1.y * k0.y + q1.z * k0.z + q1.w * k0.w;
            a11 += q1.x * k1.x + q1.y * k1.y + q1.z * k1.z + q1.w * k1.w;
        }
        S.sc[tr][tc]           = a00 * 0.125f;
        S.sc[tr][tc + 16]      = a01 * 0.125f;
        S.sc[tr + 16][tc]      = a10 * 0.125f;
        S.sc[tr + 16][tc + 16] = a11 * 0.125f;
    }
    for (int e = tid; e < 2048; e += 256) {
        int t = e >> 6, dd = e & 63;
        S.sqT[dd][t] = sigma_fn(S.qs[t][dd]);
    }
    __syncthreads();

    // ---- phase 5: warp-parallel softmax + denom ----
    #pragma unroll
    for (int r = 0; r < 4; r++) {
        int t = warp * 4 + r;
        float v = (lane <= t) ? S.sc[t][lane] : -1e30f;
        float m = v;
        #pragma unroll
        for (int o = 16; o > 0; o >>= 1) m = fmaxf(m, __shfl_xor_sync(0xFFFFFFFFu, m, o));
        float ex = (lane <= t) ? __expf(v - m) : 0.f;
        float ssum = ex;
        #pragma unroll
        for (int o = 16; o > 0; o >>= 1) ssum += __shfl_xor_sync(0xFFFFFFFFu, ssum, o);
        S.sc[t][lane] = ex / ssum;
    }
    if (tid < TSEQ) {
        float acc = 0.f;
        #pragma unroll
        for (int kx = 0; kx < DHD; kx++) acc += S.sqT[kx][tid] * S.zs[kx];
        S.denom[tid] = acc;
    }
    __syncthreads();

    // ---- phase 6: out = g*(sigma_q@mem)/denom + (1-g)*(attn@v) ----
    {
        const int dc = warp;
        const int t  = lane;
        const int dd0 = dc * 8;
        float4 aA0 = {0,0,0,0}, aA1 = {0,0,0,0};
        float4 aR0 = {0,0,0,0}, aR1 = {0,0,0,0};
        #pragma unroll
        for (int tt = 0; tt < TSEQ; tt++) {
            float sv = S.sc[t][tt];
            float4 v0 = *(const float4*)&S.vs[tt][dd0];
            float4 v1 = *(const float4*)&S.vs[tt][dd0 + 4];
            aA0.x += sv * v0.x; aA0.y += sv * v0.y; aA0.z += sv * v0.z; aA0.w += sv * v0.w;
            aA1.x += sv * v1.x; aA1.y += sv * v1.y; aA1.z += sv * v1.z; aA1.w += sv * v1.w;
        }
        #pragma unroll
        for (int kx = 0; kx < DHD; kx++) {
            float sq = S.sqT[kx][t];
            float4 m0 = *(const float4*)&S.ms[kx][dd0];
            float4 m1 = *(const float4*)&S.ms[kx][dd0 + 4];
            aR0.x += sq * m0.x; aR0.y += sq * m0.y; aR0.z += sq * m0.z; aR0.w += sq * m0.w;
            aR1.x += sq * m1.x; aR1.y += sq * m1.y; aR1.z += sq * m1.z; aR1.w += sq * m1.w;
        }
        const float gi = g / S.denom[t];
        float4 o0, o1;
        o0.x = gi * aR0.x + ig * aA0.x;  o0.y = gi * aR0.y + ig * aA0.y;
        o0.z = gi * aR0.z + ig * aA0.z;  o0.w = gi * aR0.w + ig * aA0.w;
        o1.x = gi * aR1.x + ig * aA1.x;  o1.y = gi * aR1.y + ig * aA1.y;
        o1.z = gi * aR1.z + ig * aA1.z;  o1.w = gi * aR1.w + ig * aA1.w;
        *(float4*)&S.qs[t][dd0]     = o0;
        *(float4*)&S.qs[t][dd0 + 4] = o1;
    }
    __syncthreads();

    // ---- phase 7: coalesced fp16 writeback (plain layout) ----
    for (int e = tid; e < 1024; e += 256) {
        int t = e >> 5, dd = (e & 31) * 2;
        __half2 h = __floats2half2_rn(S.qs[t][dd], S.qs[t][dd + 1]);
        *(__half2*)(out_mid + (size_t)(row_base + t * 576) * 1024 + head * 64 + dd) = h;
    }
}

// ---------------- launch ----------------
extern "C" void kernel_launch(void* const* d_in, const int* in_sizes, int n_in,
                              void* d_out, int out_size) {
    const float* x        = (const float*)d_in[0];
    const float* mem      = (const float*)d_in[1];
    const float* z        = (const float*)d_in[2];
    const float* W_qkv    = (const float*)d_in[3];
    const float* W_out    = (const float*)d_in[4];
    const float* b_out    = (const float*)d_in[5];
    const float* mem_beta = (const float*)d_in[6];
    const float* inv_freq = (const float*)d_in[7];

    float* x_out = (float*)d_out;
    float* nmem  = x_out + 37748736UL;
    float* nz    = x_out + 113246208UL;

    __half *qkv = nullptr, *mid = nullptr, *xh = nullptr, *wt = nullptr;
    float2* rope = nullptr;
    cudaGetSymbolAddress((void**)&qkv, g_qkv_h);
    cudaGetSymbolAddress((void**)&mid, g_mid_h);
    cudaGetSymbolAddress((void**)&xh, g_x_h);
    cudaGetSymbolAddress((void**)&wt, g_wt_h);
    cudaGetSymbolAddress((void**)&rope, g_rope);
    __half* wt_qkv = wt;
    __half* wt_out = wt + 3145728UL;

    cudaFuncSetAttribute(gemm_h<true>, cudaFuncAttributeMaxDynamicSharedMemorySize, GEMM_SMEM);
    cudaFuncSetAttribute(gemm_h<false>, cudaFuncAttributeMaxDynamicSharedMemorySize, GEMM_SMEM);
    cudaFuncSetAttribute(attn_kernel, cudaFuncAttributeMaxDynamicSharedMemorySize,
                         (int)sizeof(AttnSmem));

    const int M = 36864, K = 1024;

    convert_x_kernel<<<(M * K / 8 + 255) / 256, 256>>>((const float4*)x, (uint4*)xh, M * K / 8);
    transpose_half_kernel<<<dim3(3072 / 32, 1024 / 32), 256>>>(W_qkv, wt_qkv, 1024, 3072);
    transpose_half_kernel<<<dim3(1024 / 32, 1024 / 32), 256>>>(W_out, wt_out, 1024, 1024);
    rope_table_kernel<<<1, 1024>>>(inv_freq, rope);

    gemm_h<true><<<dim3(3072 / 128, M / 128), 256, GEMM_SMEM>>>(
        3072, K, xh, wt_qkv, qkv, nullptr);

    attn_kernel<<<18432, 256, sizeof(AttnSmem)>>>(
        qkv, mem, z, mem_beta, rope, mid, nmem, nz);

    gemm_h<false><<<dim3(1024 / 128, M / 128), 256, GEMM_SMEM>>>(
        1024, K, mid, wt_out, x_out, b_out);
}